// round 4
// baseline (speedup 1.0000x reference)
#include <cuda_runtime.h>
#include <math.h>

#define MAX_E 100000
#define S3 0.5773502691896258f
#define S2 0.7071067811865476f

// Scratch (static device globals: allowed, no runtime allocation)
__device__ float g_h[(size_t)MAX_E * 64];    // 25.6 MB : silu(LN(s@W1+b1))
__device__ float g_w[(size_t)MAX_E * 896];   // 358 MB  : per-edge TP weights

__device__ __forceinline__ float warp_sum(float v) {
#pragma unroll
    for (int o = 16; o > 0; o >>= 1) v += __shfl_xor_sync(0xffffffffu, v, o);
    return v;
}

// ---------------------------------------------------------------------------
// K1: h = silu(LN(edge_scalars @ rad_W1 + b1))  -> g_h
// 64 edges / block, 256 threads. W1 (16KB) staged in smem.
// ---------------------------------------------------------------------------
__global__ __launch_bounds__(256) void k1_rad(
    const float* __restrict__ es, const float* __restrict__ W1,
    const float* __restrict__ b1, const float* __restrict__ lg,
    const float* __restrict__ lb, int E)
{
    __shared__ float s_sm[64 * 65];
    __shared__ float W1_sm[64 * 64];
    __shared__ float red[128];
    const int tid = threadIdx.x;
    const int e0 = blockIdx.x * 64;

    for (int idx = tid; idx < 4096; idx += 256) W1_sm[idx] = W1[idx];
    for (int idx = tid; idx < 4096; idx += 256) {
        int e = idx >> 6, i = idx & 63;
        int ge = e0 + e;
        s_sm[e * 65 + i] = (ge < E) ? es[(size_t)ge * 64 + i] : 0.f;
    }
    __syncthreads();

    const int j = tid & 63, eg = tid >> 6;   // j: output dim, eg: edge group (16 edges each)
    float acc[16];
#pragma unroll
    for (int t = 0; t < 16; t++) acc[t] = 0.f;
    for (int i = 0; i < 64; i++) {
        float w = W1_sm[i * 64 + j];
#pragma unroll
        for (int t = 0; t < 16; t++) acc[t] += s_sm[(eg * 16 + t) * 65 + i] * w;
    }
    const float bj = b1[j];
    __syncthreads();                          // done reading s_sm; reuse as h tile
#pragma unroll
    for (int t = 0; t < 16; t++) s_sm[(eg * 16 + t) * 65 + j] = acc[t] + bj;
    __syncthreads();

    if (tid < 64) {
        float s = 0.f, q = 0.f;
        for (int c = 0; c < 64; c++) { float v = s_sm[tid * 65 + c]; s += v; q += v * v; }
        float mu = s * (1.f / 64.f);
        float var = q * (1.f / 64.f) - mu * mu;
        red[tid] = mu;
        red[64 + tid] = rsqrtf(var + 1e-5f);
    }
    __syncthreads();
    for (int idx = tid; idx < 4096; idx += 256) {
        int e = idx >> 6, c = idx & 63;
        int ge = e0 + e;
        if (ge < E) {
            float v = (s_sm[e * 65 + c] - red[e]) * red[64 + e] * lg[c] + lb[c];
            v = v / (1.f + expf(-v));         // silu
            g_h[(size_t)ge * 64 + c] = v;
        }
    }
}

// ---------------------------------------------------------------------------
// K2: g_w = g_h @ rad_W2 + rad_offset   (E x 64) @ (64 x 896)
// Tile 64(M) x 64(N), K=64 single pass, 4x4 micro-tile per thread.
// ---------------------------------------------------------------------------
__global__ __launch_bounds__(256) void k2_radw(
    const float* __restrict__ W2, const float* __restrict__ off, int E)
{
    __shared__ float h_sm[64 * 65];
    __shared__ float w_sm[64 * 68];
    const int tid = threadIdx.x;
    const int e0 = blockIdx.x * 64;
    const int n0 = blockIdx.y * 64;

    for (int idx = tid; idx < 4096; idx += 256) {
        int e = idx >> 6, k = idx & 63;
        int ge = e0 + e;
        h_sm[e * 65 + k] = (ge < E) ? g_h[(size_t)ge * 64 + k] : 0.f;
    }
    for (int idx = tid; idx < 4096; idx += 256) {
        int k = idx >> 6, c = idx & 63;
        w_sm[k * 68 + c] = W2[(size_t)k * 896 + n0 + c];
    }
    __syncthreads();

    const int tx = tid & 15, ty = tid >> 4;
    float acc[4][4];
#pragma unroll
    for (int i = 0; i < 4; i++)
#pragma unroll
        for (int jq = 0; jq < 4; jq++) acc[i][jq] = 0.f;

    for (int k = 0; k < 64; k++) {
        float a[4], b[4];
#pragma unroll
        for (int i = 0; i < 4; i++) a[i] = h_sm[(ty * 4 + i) * 65 + k];
#pragma unroll
        for (int jq = 0; jq < 4; jq++) b[jq] = w_sm[k * 68 + tx * 4 + jq];
#pragma unroll
        for (int i = 0; i < 4; i++)
#pragma unroll
            for (int jq = 0; jq < 4; jq++) acc[i][jq] += a[i] * b[jq];
    }

    float o[4];
#pragma unroll
    for (int jq = 0; jq < 4; jq++) o[jq] = off[n0 + tx * 4 + jq];
#pragma unroll
    for (int i = 0; i < 4; i++) {
        int ge = e0 + ty * 4 + i;
        if (ge < E) {
            float4 r = make_float4(acc[i][0] + o[0], acc[i][1] + o[1],
                                   acc[i][2] + o[2], acc[i][3] + o[3]);
            *reinterpret_cast<float4*>(&g_w[(size_t)ge * 896 + n0 + tx * 4]) = r;
        }
    }
}

// ---------------------------------------------------------------------------
// K3a: scalar path. s = [x0*y0*wA , (1/sqrt3)*(x1.y1)*wD] @ lin_Ws + bs, then LN.
// 64 edges / block, full N=256, K=384 in 12 chunks of 32. A built on the fly.
// 8x8 micro-tile; layernorm done fully warp-local (warp ty owns edges ty*8..+7).
// ---------------------------------------------------------------------------
__global__ __launch_bounds__(256) void k3a_scalar(
    const float* __restrict__ node, const float* __restrict__ eattr,
    const float* __restrict__ Ws, const float* __restrict__ bs,
    const float* __restrict__ gs, const float* __restrict__ gb,
    float* __restrict__ out, int E)
{
    __shared__ float A_sm[64 * 33];
    __shared__ float W_sm[32 * 256];
    __shared__ float y_sm[64 * 4];
    const int tid = threadIdx.x;
    const int tx = tid & 31, ty = tid >> 5;
    const int e0 = blockIdx.x * 64;

    {
        int e = tid >> 2;
        int ge = e0 + e;
        y_sm[tid] = (ge < E) ? eattr[(size_t)ge * 4 + (tid & 3)] : 0.f;
    }

    float acc[8][8];
#pragma unroll
    for (int i = 0; i < 8; i++)
#pragma unroll
        for (int jq = 0; jq < 8; jq++) acc[i][jq] = 0.f;

    for (int q = 0; q < 12; q++) {
        __syncthreads();
        // build A chunk [64 edges x 32 u]
        for (int idx = tid; idx < 2048; idx += 256) {
            int e = idx >> 5, jj = idx & 31;
            int ge = e0 + e;
            float val = 0.f;
            if (ge < E) {
                if (q < 8) {                      // u in [0,256): x0*y0*wA
                    int u = q * 32 + jj;
                    val = node[(size_t)ge * 640 + u] * y_sm[e * 4] *
                          g_w[(size_t)ge * 896 + u];
                } else {                          // u in [256,384): c3*(x1.y1)*wD
                    int jp = (q - 8) * 32 + jj;
                    const float* xp = node + (size_t)ge * 640 + 256 + 3 * jp;
                    float d = xp[0] * y_sm[e * 4 + 1] + xp[1] * y_sm[e * 4 + 2] +
                              xp[2] * y_sm[e * 4 + 3];
                    val = S3 * d * g_w[(size_t)ge * 896 + 640 + jp];
                }
            }
            A_sm[e * 33 + jj] = val;
        }
        // stage Ws chunk [32 x 256]
        for (int idx = tid; idx < 8192; idx += 256) {
            int k = idx >> 8, c = idx & 255;
            W_sm[idx] = Ws[(size_t)(q * 32 + k) * 256 + c];
        }
        __syncthreads();

        for (int k = 0; k < 32; k++) {
            float a[8], b[8];
#pragma unroll
            for (int i = 0; i < 8; i++) a[i] = A_sm[(ty * 8 + i) * 33 + k];
#pragma unroll
            for (int jq = 0; jq < 8; jq++) b[jq] = W_sm[k * 256 + tx + 32 * jq];
#pragma unroll
            for (int i = 0; i < 8; i++)
#pragma unroll
                for (int jq = 0; jq < 8; jq++) acc[i][jq] += a[i] * b[jq];
        }
    }

    // epilogue: + bias, layernorm over 256 cols (all within warp ty), write
    float bsv[8], gsv[8], gbv[8];
#pragma unroll
    for (int jq = 0; jq < 8; jq++) {
        int c = tx + 32 * jq;
        bsv[jq] = bs[c]; gsv[jq] = gs[c]; gbv[jq] = gb[c];
    }
#pragma unroll
    for (int i = 0; i < 8; i++) {
        float s = 0.f, qq = 0.f;
#pragma unroll
        for (int jq = 0; jq < 8; jq++) {
            float v = acc[i][jq] + bsv[jq];
            acc[i][jq] = v;
            s += v; qq += v * v;
        }
        s = warp_sum(s);
        qq = warp_sum(qq);
        float mu = s * (1.f / 256.f);
        float var = qq * (1.f / 256.f) - mu * mu;
        float rstd = rsqrtf(var + 1e-5f);
        int ge = e0 + ty * 8 + i;
        if (ge < E) {
#pragma unroll
            for (int jq = 0; jq < 8; jq++) {
                int c = tx + 32 * jq;
                out[(size_t)ge * 640 + c] = (acc[i][jq] - mu) * rstd * gsv[jq] + gbv[jq];
            }
        }
    }
}

// ---------------------------------------------------------------------------
// K3b: vector path via algebraic fusion:
//   Ra[e,k]   = sum_{u<256} Wv[u,k]      * x0[e,u]*wB[e,u]
//   Rb[e,k,m] = sum_{u<128} Wv[256+u,k]  * wC[e,u]*x1[e,u,m]
//   Rc[e,k,m] = sum_{u<128} Wv[384+u,k]  * wE[e,u]*x1[e,u,m]
//   v[e,k,:]  = Ra*y1 + y0*Rb + (1/sqrt2)*cross(Rc, y1)
// then norm over all 384 elements (warp-local) and scale by ln_gv[k].
// 16 edges / block, full N=128. 7 accumulator planes, 2x4 micro per thread.
// ---------------------------------------------------------------------------
__global__ __launch_bounds__(256) void k3b_vector(
    const float* __restrict__ node, const float* __restrict__ eattr,
    const float* __restrict__ Wv, const float* __restrict__ gv,
    float* __restrict__ out, int E)
{
    __shared__ float A_sm[3072];       // A1: [e*64+j]; A3: [(e*64+j)*3+m]
    __shared__ float Wv_sm[8192];      // [64 k][128 c]
    __shared__ float y_sm[64];
    const int tid = threadIdx.x;
    const int tx = tid & 31, ty = tid >> 5;
    const int e0 = blockIdx.x * 16;

    if (tid < 64) {
        int e = tid >> 2;
        int ge = e0 + e;
        y_sm[tid] = (ge < E) ? eattr[(size_t)ge * 4 + (tid & 3)] : 0.f;
    }

    float acc[2][4][7];
#pragma unroll
    for (int ii = 0; ii < 2; ii++)
#pragma unroll
        for (int jq = 0; jq < 4; jq++)
#pragma unroll
            for (int p = 0; p < 7; p++) acc[ii][jq][p] = 0.f;

    // ---- Part A: Ra (plane 0), u in [0,256), 4 chunks of 64 ----
    for (int q = 0; q < 4; q++) {
        __syncthreads();
        for (int idx = tid; idx < 1024; idx += 256) {
            int e = idx >> 6, jj = idx & 63;
            int ge = e0 + e;
            int u = q * 64 + jj;
            A_sm[idx] = (ge < E)
                ? node[(size_t)ge * 640 + u] * g_w[(size_t)ge * 896 + 256 + u]
                : 0.f;
        }
        for (int idx = tid; idx < 8192; idx += 256)
            Wv_sm[idx] = Wv[(size_t)(q * 64) * 128 + idx];
        __syncthreads();
        for (int k = 0; k < 64; k++) {
            float b[4];
#pragma unroll
            for (int jq = 0; jq < 4; jq++) b[jq] = Wv_sm[k * 128 + tx + 32 * jq];
            float a0 = A_sm[ty * 64 + k];
            float a1 = A_sm[(ty + 8) * 64 + k];
#pragma unroll
            for (int jq = 0; jq < 4; jq++) {
                acc[0][jq][0] += a0 * b[jq];
                acc[1][jq][0] += a1 * b[jq];
            }
        }
    }

    // ---- Parts B (planes 1..3, wC, Wv rows 256+) and C (planes 4..6, wE, rows 384+) ----
#pragma unroll
    for (int part = 0; part < 2; part++) {
        const int wofs = (part == 0) ? 512 : 768;
        const int vrow = (part == 0) ? 256 : 384;
        const int pb = (part == 0) ? 1 : 4;
        for (int q = 0; q < 2; q++) {
            __syncthreads();
            for (int idx = tid; idx < 1024; idx += 256) {
                int e = idx >> 6, jj = idx & 63;
                int ge = e0 + e;
                int jp = q * 64 + jj;
                float w = 0.f, x0v = 0.f, x1v = 0.f, x2v = 0.f;
                if (ge < E) {
                    w = g_w[(size_t)ge * 896 + wofs + jp];
                    const float* xp = node + (size_t)ge * 640 + 256 + 3 * jp;
                    x0v = xp[0]; x1v = xp[1]; x2v = xp[2];
                }
                A_sm[idx * 3 + 0] = x0v * w;
                A_sm[idx * 3 + 1] = x1v * w;
                A_sm[idx * 3 + 2] = x2v * w;
            }
            for (int idx = tid; idx < 8192; idx += 256)
                Wv_sm[idx] = Wv[(size_t)(vrow + q * 64) * 128 + idx];
            __syncthreads();
            for (int k = 0; k < 64; k++) {
                float b[4];
#pragma unroll
                for (int jq = 0; jq < 4; jq++) b[jq] = Wv_sm[k * 128 + tx + 32 * jq];
                int ba = (ty * 64 + k) * 3, bb = ((ty + 8) * 64 + k) * 3;
                float a00 = A_sm[ba], a01 = A_sm[ba + 1], a02 = A_sm[ba + 2];
                float a10 = A_sm[bb], a11 = A_sm[bb + 1], a12 = A_sm[bb + 2];
#pragma unroll
                for (int jq = 0; jq < 4; jq++) {
                    acc[0][jq][pb + 0] += a00 * b[jq];
                    acc[0][jq][pb + 1] += a01 * b[jq];
                    acc[0][jq][pb + 2] += a02 * b[jq];
                    acc[1][jq][pb + 0] += a10 * b[jq];
                    acc[1][jq][pb + 1] += a11 * b[jq];
                    acc[1][jq][pb + 2] += a12 * b[jq];
                }
            }
        }
    }

    // ---- Combine + norm + write ----
    float gvv[4];
#pragma unroll
    for (int jq = 0; jq < 4; jq++) gvv[jq] = gv[tx + 32 * jq];

#pragma unroll
    for (int ii = 0; ii < 2; ii++) {
        int e = ty + 8 * ii;
        int ge = e0 + e;
        float ya = y_sm[e * 4 + 0];
        float y0v = y_sm[e * 4 + 1], y1v = y_sm[e * 4 + 2], y2v = y_sm[e * 4 + 3];
        float v[4][3];
        float sq = 0.f;
#pragma unroll
        for (int jq = 0; jq < 4; jq++) {
            float Ra = acc[ii][jq][0];
            float rb0 = acc[ii][jq][1], rb1 = acc[ii][jq][2], rb2 = acc[ii][jq][3];
            float rc0 = acc[ii][jq][4], rc1 = acc[ii][jq][5], rc2 = acc[ii][jq][6];
            float cr0 = rc1 * y2v - rc2 * y1v;
            float cr1 = rc2 * y0v - rc0 * y2v;
            float cr2 = rc0 * y1v - rc1 * y0v;
            v[jq][0] = Ra * y0v + ya * rb0 + S2 * cr0;
            v[jq][1] = Ra * y1v + ya * rb1 + S2 * cr1;
            v[jq][2] = Ra * y2v + ya * rb2 + S2 * cr2;
            sq += v[jq][0] * v[jq][0] + v[jq][1] * v[jq][1] + v[jq][2] * v[jq][2];
        }
        sq = warp_sum(sq);                    // warp ty owns all 128 cols of edge e
        float rstd = rsqrtf(sq * (1.f / 384.f) + 1e-5f);
        if (ge < E) {
#pragma unroll
            for (int jq = 0; jq < 4; jq++) {
                size_t base = (size_t)ge * 640 + 256 + 3 * (size_t)(tx + 32 * jq);
                out[base + 0] = v[jq][0] * rstd * gvv[jq];
                out[base + 1] = v[jq][1] * rstd * gvv[jq];
                out[base + 2] = v[jq][2] * rstd * gvv[jq];
            }
        }
    }
}

// ---------------------------------------------------------------------------
extern "C" void kernel_launch(void* const* d_in, const int* in_sizes, int n_in,
                              void* d_out, int out_size)
{
    const float* node  = (const float*)d_in[0];   // (E, 640)
    const float* eattr = (const float*)d_in[1];   // (E, 4)
    const float* escal = (const float*)d_in[2];   // (E, 64)
    const float* rW1   = (const float*)d_in[3];   // (64, 64)
    const float* rb1   = (const float*)d_in[4];   // (64,)
    const float* rlg   = (const float*)d_in[5];   // (64,)
    const float* rlb   = (const float*)d_in[6];   // (64,)
    const float* rW2   = (const float*)d_in[7];   // (64, 896)
    const float* roff  = (const float*)d_in[8];   // (896,)
    const float* Ws    = (const float*)d_in[9];   // (384, 256)
    const float* bs    = (const float*)d_in[10];  // (256,)
    const float* Wv    = (const float*)d_in[11];  // (512, 128)
    const float* gs    = (const float*)d_in[12];  // (256,)
    const float* gb    = (const float*)d_in[13];  // (256,)
    const float* gv    = (const float*)d_in[14];  // (128,)
    float* out = (float*)d_out;

    const int E = in_sizes[1] / 4;
    const int nb64 = (E + 63) / 64;
    const int nb16 = (E + 15) / 16;

    k1_rad<<<nb64, 256>>>(escal, rW1, rb1, rlg, rlb, E);
    dim3 g2(nb64, 14);
    k2_radw<<<g2, 256>>>(rW2, roff, E);
    k3a_scalar<<<nb64, 256>>>(node, eattr, Ws, bs, gs, gb, out, E);
    k3b_vector<<<nb16, 256>>>(node, eattr, Wv, gv, out, E);
}

// round 5
// speedup vs baseline: 1.0009x; 1.0009x over previous
#include <cuda_runtime.h>
#include <math.h>

#define MAX_E 100000
#define S3 0.5773502691896258f
#define S2 0.7071067811865476f

// Scratch (static device globals: allowed, no runtime allocation)
__device__ float g_h[(size_t)MAX_E * 64];    // 25.6 MB : silu(LN(s@W1+b1))
__device__ float g_w[(size_t)MAX_E * 896];   // 358 MB  : per-edge TP weights

__device__ __forceinline__ float warp_sum(float v) {
#pragma unroll
    for (int o = 16; o > 0; o >>= 1) v += __shfl_xor_sync(0xffffffffu, v, o);
    return v;
}

// ---------------------------------------------------------------------------
// K1: h = silu(LN(edge_scalars @ rad_W1 + b1))  -> g_h
// 64 edges / block, 256 threads. W1 (16KB) staged in smem.
// ---------------------------------------------------------------------------
__global__ __launch_bounds__(256) void k1_rad(
    const float* __restrict__ es, const float* __restrict__ W1,
    const float* __restrict__ b1, const float* __restrict__ lg,
    const float* __restrict__ lb, int E)
{
    __shared__ float s_sm[64 * 65];
    __shared__ float W1_sm[64 * 64];
    __shared__ float red[128];
    const int tid = threadIdx.x;
    const int e0 = blockIdx.x * 64;

    for (int idx = tid; idx < 4096; idx += 256) W1_sm[idx] = W1[idx];
    for (int idx = tid; idx < 4096; idx += 256) {
        int e = idx >> 6, i = idx & 63;
        int ge = e0 + e;
        s_sm[e * 65 + i] = (ge < E) ? es[(size_t)ge * 64 + i] : 0.f;
    }
    __syncthreads();

    const int j = tid & 63, eg = tid >> 6;   // j: output dim, eg: edge group (16 edges each)
    float acc[16];
#pragma unroll
    for (int t = 0; t < 16; t++) acc[t] = 0.f;
    for (int i = 0; i < 64; i++) {
        float w = W1_sm[i * 64 + j];
#pragma unroll
        for (int t = 0; t < 16; t++) acc[t] += s_sm[(eg * 16 + t) * 65 + i] * w;
    }
    const float bj = b1[j];
    __syncthreads();                          // done reading s_sm; reuse as h tile
#pragma unroll
    for (int t = 0; t < 16; t++) s_sm[(eg * 16 + t) * 65 + j] = acc[t] + bj;
    __syncthreads();

    if (tid < 64) {
        float s = 0.f, q = 0.f;
        for (int c = 0; c < 64; c++) { float v = s_sm[tid * 65 + c]; s += v; q += v * v; }
        float mu = s * (1.f / 64.f);
        float var = q * (1.f / 64.f) - mu * mu;
        red[tid] = mu;
        red[64 + tid] = rsqrtf(var + 1e-5f);
    }
    __syncthreads();
    for (int idx = tid; idx < 4096; idx += 256) {
        int e = idx >> 6, c = idx & 63;
        int ge = e0 + e;
        if (ge < E) {
            float v = (s_sm[e * 65 + c] - red[e]) * red[64 + e] * lg[c] + lb[c];
            v = v / (1.f + expf(-v));         // silu
            g_h[(size_t)ge * 64 + c] = v;
        }
    }
}

// ---------------------------------------------------------------------------
// K2: g_w = g_h @ rad_W2 + rad_offset   (E x 64) @ (64 x 896)
// Tile 64(M) x 64(N), K=64 single pass, 4x4 micro-tile per thread.
// ---------------------------------------------------------------------------
__global__ __launch_bounds__(256) void k2_radw(
    const float* __restrict__ W2, const float* __restrict__ off, int E)
{
    __shared__ float h_sm[64 * 65];
    __shared__ float w_sm[64 * 68];
    const int tid = threadIdx.x;
    const int e0 = blockIdx.x * 64;
    const int n0 = blockIdx.y * 64;

    for (int idx = tid; idx < 4096; idx += 256) {
        int e = idx >> 6, k = idx & 63;
        int ge = e0 + e;
        h_sm[e * 65 + k] = (ge < E) ? g_h[(size_t)ge * 64 + k] : 0.f;
    }
    for (int idx = tid; idx < 4096; idx += 256) {
        int k = idx >> 6, c = idx & 63;
        w_sm[k * 68 + c] = W2[(size_t)k * 896 + n0 + c];
    }
    __syncthreads();

    const int tx = tid & 15, ty = tid >> 4;
    float acc[4][4];
#pragma unroll
    for (int i = 0; i < 4; i++)
#pragma unroll
        for (int jq = 0; jq < 4; jq++) acc[i][jq] = 0.f;

    for (int k = 0; k < 64; k++) {
        float a[4], b[4];
#pragma unroll
        for (int i = 0; i < 4; i++) a[i] = h_sm[(ty * 4 + i) * 65 + k];
#pragma unroll
        for (int jq = 0; jq < 4; jq++) b[jq] = w_sm[k * 68 + tx * 4 + jq];
#pragma unroll
        for (int i = 0; i < 4; i++)
#pragma unroll
            for (int jq = 0; jq < 4; jq++) acc[i][jq] += a[i] * b[jq];
    }

    float o[4];
#pragma unroll
    for (int jq = 0; jq < 4; jq++) o[jq] = off[n0 + tx * 4 + jq];
#pragma unroll
    for (int i = 0; i < 4; i++) {
        int ge = e0 + ty * 4 + i;
        if (ge < E) {
            float4 r = make_float4(acc[i][0] + o[0], acc[i][1] + o[1],
                                   acc[i][2] + o[2], acc[i][3] + o[3]);
            *reinterpret_cast<float4*>(&g_w[(size_t)ge * 896 + n0 + tx * 4]) = r;
        }
    }
}

// ---------------------------------------------------------------------------
// K3a: scalar path. s = [x0*y0*wA , (1/sqrt3)*(x1.y1)*wD] @ lin_Ws + bs, then LN.
// 64 edges / block, full N=256, K=384 in 12 chunks of 32. A built on the fly.
// 8x8 micro-tile; layernorm done fully warp-local (warp ty owns edges ty*8..+7).
// ---------------------------------------------------------------------------
__global__ __launch_bounds__(256) void k3a_scalar(
    const float* __restrict__ node, const float* __restrict__ eattr,
    const float* __restrict__ Ws, const float* __restrict__ bs,
    const float* __restrict__ gs, const float* __restrict__ gb,
    float* __restrict__ out, int E)
{
    __shared__ float A_sm[64 * 33];
    __shared__ float W_sm[32 * 256];
    __shared__ float y_sm[64 * 4];
    const int tid = threadIdx.x;
    const int tx = tid & 31, ty = tid >> 5;
    const int e0 = blockIdx.x * 64;

    {
        int e = tid >> 2;
        int ge = e0 + e;
        y_sm[tid] = (ge < E) ? eattr[(size_t)ge * 4 + (tid & 3)] : 0.f;
    }

    float acc[8][8];
#pragma unroll
    for (int i = 0; i < 8; i++)
#pragma unroll
        for (int jq = 0; jq < 8; jq++) acc[i][jq] = 0.f;

    for (int q = 0; q < 12; q++) {
        __syncthreads();
        // build A chunk [64 edges x 32 u]
        for (int idx = tid; idx < 2048; idx += 256) {
            int e = idx >> 5, jj = idx & 31;
            int ge = e0 + e;
            float val = 0.f;
            if (ge < E) {
                if (q < 8) {                      // u in [0,256): x0*y0*wA
                    int u = q * 32 + jj;
                    val = node[(size_t)ge * 640 + u] * y_sm[e * 4] *
                          g_w[(size_t)ge * 896 + u];
                } else {                          // u in [256,384): c3*(x1.y1)*wD
                    int jp = (q - 8) * 32 + jj;
                    const float* xp = node + (size_t)ge * 640 + 256 + 3 * jp;
                    float d = xp[0] * y_sm[e * 4 + 1] + xp[1] * y_sm[e * 4 + 2] +
                              xp[2] * y_sm[e * 4 + 3];
                    val = S3 * d * g_w[(size_t)ge * 896 + 640 + jp];
                }
            }
            A_sm[e * 33 + jj] = val;
        }
        // stage Ws chunk [32 x 256]
        for (int idx = tid; idx < 8192; idx += 256) {
            int k = idx >> 8, c = idx & 255;
            W_sm[idx] = Ws[(size_t)(q * 32 + k) * 256 + c];
        }
        __syncthreads();

        for (int k = 0; k < 32; k++) {
            float a[8], b[8];
#pragma unroll
            for (int i = 0; i < 8; i++) a[i] = A_sm[(ty * 8 + i) * 33 + k];
#pragma unroll
            for (int jq = 0; jq < 8; jq++) b[jq] = W_sm[k * 256 + tx + 32 * jq];
#pragma unroll
            for (int i = 0; i < 8; i++)
#pragma unroll
                for (int jq = 0; jq < 8; jq++) acc[i][jq] += a[i] * b[jq];
        }
    }

    // epilogue: + bias, layernorm over 256 cols (all within warp ty), write
    float bsv[8], gsv[8], gbv[8];
#pragma unroll
    for (int jq = 0; jq < 8; jq++) {
        int c = tx + 32 * jq;
        bsv[jq] = bs[c]; gsv[jq] = gs[c]; gbv[jq] = gb[c];
    }
#pragma unroll
    for (int i = 0; i < 8; i++) {
        float s = 0.f, qq = 0.f;
#pragma unroll
        for (int jq = 0; jq < 8; jq++) {
            float v = acc[i][jq] + bsv[jq];
            acc[i][jq] = v;
            s += v; qq += v * v;
        }
        s = warp_sum(s);
        qq = warp_sum(qq);
        float mu = s * (1.f / 256.f);
        float var = qq * (1.f / 256.f) - mu * mu;
        float rstd = rsqrtf(var + 1e-5f);
        int ge = e0 + ty * 8 + i;
        if (ge < E) {
#pragma unroll
            for (int jq = 0; jq < 8; jq++) {
                int c = tx + 32 * jq;
                out[(size_t)ge * 640 + c] = (acc[i][jq] - mu) * rstd * gsv[jq] + gbv[jq];
            }
        }
    }
}

// ---------------------------------------------------------------------------
// K3b: vector path via algebraic fusion:
//   Ra[e,k]   = sum_{u<256} Wv[u,k]      * x0[e,u]*wB[e,u]
//   Rb[e,k,m] = sum_{u<128} Wv[256+u,k]  * wC[e,u]*x1[e,u,m]
//   Rc[e,k,m] = sum_{u<128} Wv[384+u,k]  * wE[e,u]*x1[e,u,m]
//   v[e,k,:]  = Ra*y1 + y0*Rb + (1/sqrt2)*cross(Rc, y1)
// then norm over all 384 elements (warp-local) and scale by ln_gv[k].
// 16 edges / block, full N=128. 7 accumulator planes, 2x4 micro per thread.
// ---------------------------------------------------------------------------
__global__ __launch_bounds__(256) void k3b_vector(
    const float* __restrict__ node, const float* __restrict__ eattr,
    const float* __restrict__ Wv, const float* __restrict__ gv,
    float* __restrict__ out, int E)
{
    __shared__ float A_sm[3072];       // A1: [e*64+j]; A3: [(e*64+j)*3+m]
    __shared__ float Wv_sm[8192];      // [64 k][128 c]
    __shared__ float y_sm[64];
    const int tid = threadIdx.x;
    const int tx = tid & 31, ty = tid >> 5;
    const int e0 = blockIdx.x * 16;

    if (tid < 64) {
        int e = tid >> 2;
        int ge = e0 + e;
        y_sm[tid] = (ge < E) ? eattr[(size_t)ge * 4 + (tid & 3)] : 0.f;
    }

    float acc[2][4][7];
#pragma unroll
    for (int ii = 0; ii < 2; ii++)
#pragma unroll
        for (int jq = 0; jq < 4; jq++)
#pragma unroll
            for (int p = 0; p < 7; p++) acc[ii][jq][p] = 0.f;

    // ---- Part A: Ra (plane 0), u in [0,256), 4 chunks of 64 ----
    for (int q = 0; q < 4; q++) {
        __syncthreads();
        for (int idx = tid; idx < 1024; idx += 256) {
            int e = idx >> 6, jj = idx & 63;
            int ge = e0 + e;
            int u = q * 64 + jj;
            A_sm[idx] = (ge < E)
                ? node[(size_t)ge * 640 + u] * g_w[(size_t)ge * 896 + 256 + u]
                : 0.f;
        }
        for (int idx = tid; idx < 8192; idx += 256)
            Wv_sm[idx] = Wv[(size_t)(q * 64) * 128 + idx];
        __syncthreads();
        for (int k = 0; k < 64; k++) {
            float b[4];
#pragma unroll
            for (int jq = 0; jq < 4; jq++) b[jq] = Wv_sm[k * 128 + tx + 32 * jq];
            float a0 = A_sm[ty * 64 + k];
            float a1 = A_sm[(ty + 8) * 64 + k];
#pragma unroll
            for (int jq = 0; jq < 4; jq++) {
                acc[0][jq][0] += a0 * b[jq];
                acc[1][jq][0] += a1 * b[jq];
            }
        }
    }

    // ---- Parts B (planes 1..3, wC, Wv rows 256+) and C (planes 4..6, wE, rows 384+) ----
#pragma unroll
    for (int part = 0; part < 2; part++) {
        const int wofs = (part == 0) ? 512 : 768;
        const int vrow = (part == 0) ? 256 : 384;
        const int pb = (part == 0) ? 1 : 4;
        for (int q = 0; q < 2; q++) {
            __syncthreads();
            for (int idx = tid; idx < 1024; idx += 256) {
                int e = idx >> 6, jj = idx & 63;
                int ge = e0 + e;
                int jp = q * 64 + jj;
                float w = 0.f, x0v = 0.f, x1v = 0.f, x2v = 0.f;
                if (ge < E) {
                    w = g_w[(size_t)ge * 896 + wofs + jp];
                    const float* xp = node + (size_t)ge * 640 + 256 + 3 * jp;
                    x0v = xp[0]; x1v = xp[1]; x2v = xp[2];
                }
                A_sm[idx * 3 + 0] = x0v * w;
                A_sm[idx * 3 + 1] = x1v * w;
                A_sm[idx * 3 + 2] = x2v * w;
            }
            for (int idx = tid; idx < 8192; idx += 256)
                Wv_sm[idx] = Wv[(size_t)(vrow + q * 64) * 128 + idx];
            __syncthreads();
            for (int k = 0; k < 64; k++) {
                float b[4];
#pragma unroll
                for (int jq = 0; jq < 4; jq++) b[jq] = Wv_sm[k * 128 + tx + 32 * jq];
                int ba = (ty * 64 + k) * 3, bb = ((ty + 8) * 64 + k) * 3;
                float a00 = A_sm[ba], a01 = A_sm[ba + 1], a02 = A_sm[ba + 2];
                float a10 = A_sm[bb], a11 = A_sm[bb + 1], a12 = A_sm[bb + 2];
#pragma unroll
                for (int jq = 0; jq < 4; jq++) {
                    acc[0][jq][pb + 0] += a00 * b[jq];
                    acc[0][jq][pb + 1] += a01 * b[jq];
                    acc[0][jq][pb + 2] += a02 * b[jq];
                    acc[1][jq][pb + 0] += a10 * b[jq];
                    acc[1][jq][pb + 1] += a11 * b[jq];
                    acc[1][jq][pb + 2] += a12 * b[jq];
                }
            }
        }
    }

    // ---- Combine + norm + write ----
    float gvv[4];
#pragma unroll
    for (int jq = 0; jq < 4; jq++) gvv[jq] = gv[tx + 32 * jq];

#pragma unroll
    for (int ii = 0; ii < 2; ii++) {
        int e = ty + 8 * ii;
        int ge = e0 + e;
        float ya = y_sm[e * 4 + 0];
        float y0v = y_sm[e * 4 + 1], y1v = y_sm[e * 4 + 2], y2v = y_sm[e * 4 + 3];
        float v[4][3];
        float sq = 0.f;
#pragma unroll
        for (int jq = 0; jq < 4; jq++) {
            float Ra = acc[ii][jq][0];
            float rb0 = acc[ii][jq][1], rb1 = acc[ii][jq][2], rb2 = acc[ii][jq][3];
            float rc0 = acc[ii][jq][4], rc1 = acc[ii][jq][5], rc2 = acc[ii][jq][6];
            float cr0 = rc1 * y2v - rc2 * y1v;
            float cr1 = rc2 * y0v - rc0 * y2v;
            float cr2 = rc0 * y1v - rc1 * y0v;
            v[jq][0] = Ra * y0v + ya * rb0 + S2 * cr0;
            v[jq][1] = Ra * y1v + ya * rb1 + S2 * cr1;
            v[jq][2] = Ra * y2v + ya * rb2 + S2 * cr2;
            sq += v[jq][0] * v[jq][0] + v[jq][1] * v[jq][1] + v[jq][2] * v[jq][2];
        }
        sq = warp_sum(sq);                    // warp ty owns all 128 cols of edge e
        float rstd = rsqrtf(sq * (1.f / 384.f) + 1e-5f);
        if (ge < E) {
#pragma unroll
            for (int jq = 0; jq < 4; jq++) {
                size_t base = (size_t)ge * 640 + 256 + 3 * (size_t)(tx + 32 * jq);
                out[base + 0] = v[jq][0] * rstd * gvv[jq];
                out[base + 1] = v[jq][1] * rstd * gvv[jq];
                out[base + 2] = v[jq][2] * rstd * gvv[jq];
            }
        }
    }
}

// ---------------------------------------------------------------------------
extern "C" void kernel_launch(void* const* d_in, const int* in_sizes, int n_in,
                              void* d_out, int out_size)
{
    const float* node  = (const float*)d_in[0];   // (E, 640)
    const float* eattr = (const float*)d_in[1];   // (E, 4)
    const float* escal = (const float*)d_in[2];   // (E, 64)
    const float* rW1   = (const float*)d_in[3];   // (64, 64)
    const float* rb1   = (const float*)d_in[4];   // (64,)
    const float* rlg   = (const float*)d_in[5];   // (64,)
    const float* rlb   = (const float*)d_in[6];   // (64,)
    const float* rW2   = (const float*)d_in[7];   // (64, 896)
    const float* roff  = (const float*)d_in[8];   // (896,)
    const float* Ws    = (const float*)d_in[9];   // (384, 256)
    const float* bs    = (const float*)d_in[10];  // (256,)
    const float* Wv    = (const float*)d_in[11];  // (512, 128)
    const float* gs    = (const float*)d_in[12];  // (256,)
    const float* gb    = (const float*)d_in[13];  // (256,)
    const float* gv    = (const float*)d_in[14];  // (128,)
    float* out = (float*)d_out;

    const int E = in_sizes[1] / 4;
    const int nb64 = (E + 63) / 64;
    const int nb16 = (E + 15) / 16;

    k1_rad<<<nb64, 256>>>(escal, rW1, rb1, rlg, rlb, E);
    dim3 g2(nb64, 14);
    k2_radw<<<g2, 256>>>(rW2, roff, E);
    k3a_scalar<<<nb64, 256>>>(node, eattr, Ws, bs, gs, gb, out, E);
    k3b_vector<<<nb16, 256>>>(node, eattr, Wv, gv, out, E);
}

// round 7
// speedup vs baseline: 1.8353x; 1.8336x over previous
#include <cuda_runtime.h>
#include <math.h>
#include <stdint.h>

#define S3 0.5773502691896258f
#define S2 0.7071067811865476f
#define EPS 1e-5f
#define SR 68   // smem row stride (floats): bank = 4*row + col -> conflict-free frags

// per-edge TP weights scratch (static device global: allowed)
__device__ float g_w[(size_t)100000 * 896];

__device__ __forceinline__ float tf32r(float x) {
    uint32_t u;
    asm("cvt.rna.tf32.f32 %0, %1;" : "=r"(u) : "f"(x));
    return __uint_as_float(u);
}

// mma.sync m16n8k8 tf32: D += A(16x8) * B(8x8), fp32 accum. Baseline PTX (sm_80+).
__device__ __forceinline__ void mma8(float d[4], const uint32_t a[4], const uint32_t b[2]) {
    asm volatile(
        "mma.sync.aligned.m16n8k8.row.col.f32.tf32.tf32.f32 "
        "{%0,%1,%2,%3}, {%4,%5,%6,%7}, {%8,%9}, {%0,%1,%2,%3};"
        : "+f"(d[0]), "+f"(d[1]), "+f"(d[2]), "+f"(d[3])
        : "r"(a[0]), "r"(a[1]), "r"(a[2]), "r"(a[3]), "r"(b[0]), "r"(b[1]));
}
// A fragment (row-major 16x8 at row r0, k0): a0(qr,qc) a1(qr+8,qc) a2(qr,qc+4) a3(qr+8,qc+4)
__device__ __forceinline__ void ldA(uint32_t a[4], const float* As, int r0, int k0, int qr, int qc) {
    const float* p = As + (r0 + qr) * SR + k0 + qc;
    a[0] = __float_as_uint(p[0]);
    a[1] = __float_as_uint(p[8 * SR]);
    a[2] = __float_as_uint(p[4]);
    a[3] = __float_as_uint(p[8 * SR + 4]);
}
// B fragment (col-major 8x8; Bt stored [n][k]): b0(k=qc,n=qr) b1(k=qc+4,n=qr)
__device__ __forceinline__ void ldB(uint32_t b[2], const float* Bs, int n0, int k0, int qr, int qc) {
    const float* p = Bs + (n0 + qr) * SR + k0 + qc;
    b[0] = __float_as_uint(p[0]);
    b[1] = __float_as_uint(p[4]);
}
__device__ __forceinline__ float quad_sum(float v) {
    v += __shfl_xor_sync(0xffffffffu, v, 1);
    v += __shfl_xor_sync(0xffffffffu, v, 2);
    return v;
}

// ---------------------------------------------------------------------------
// F1: fused rad-MLP.  128 edges/block, 8 warps.
//   MMA1: hraw = es@W1 (M128,N64,K64); epi: h = silu(LN(hraw+b1)) -> A tile
//   7 passes: g_w[:, p*128..+128] = h@W2 + roff
// ---------------------------------------------------------------------------
#define F1_SMEM ((2 * 128 * SR + 512) * 4)
__global__ __launch_bounds__(256) void f1_kw(
    const float* __restrict__ es, const float* __restrict__ W1,
    const float* __restrict__ b1, const float* __restrict__ lg,
    const float* __restrict__ lb, const float* __restrict__ W2,
    const float* __restrict__ roff, int E)
{
    extern __shared__ float sm[];
    float* As   = sm;                 // 128 x SR
    float* Bs   = As + 128 * SR;      // 128 x SR
    float* redS = Bs + 128 * SR;      // 128*2
    float* redQ = redS + 256;         // 128*2
    const int tid = threadIdx.x, wid = tid >> 5, lane = tid & 31;
    const int qr = lane >> 2, qc = lane & 3;
    const int e0 = blockIdx.x * 128;
    const int wm = wid & 3, wn = wid >> 2;

    for (int idx = tid; idx < 8192; idx += 256) {
        int e = idx >> 6, c = idx & 63, ge = e0 + e;
        As[e * SR + c] = tf32r(ge < E ? es[(size_t)ge * 64 + c] : 0.f);
    }
    for (int idx = tid; idx < 4096; idx += 256) {
        int n = idx & 63, k = idx >> 6;
        Bs[n * SR + k] = tf32r(W1[k * 64 + n]);
    }
    __syncthreads();

    {   // ---- MMA1: warp tile 32 rows x 32 cols ----
        const int r0 = wm * 32, n0 = wn * 32;
        float acc[2][4][4];
#pragma unroll
        for (int mt = 0; mt < 2; mt++)
#pragma unroll
            for (int nt = 0; nt < 4; nt++)
#pragma unroll
                for (int f = 0; f < 4; f++) acc[mt][nt][f] = 0.f;
#pragma unroll
        for (int ks = 0; ks < 8; ks++) {
            int k0 = ks * 8;
            uint32_t a[2][4], b[4][2];
            ldA(a[0], As, r0, k0, qr, qc);
            ldA(a[1], As, r0 + 16, k0, qr, qc);
#pragma unroll
            for (int nt = 0; nt < 4; nt++) ldB(b[nt], Bs, n0 + nt * 8, k0, qr, qc);
#pragma unroll
            for (int mt = 0; mt < 2; mt++)
#pragma unroll
                for (int nt = 0; nt < 4; nt++) mma8(acc[mt][nt], a[mt], b[nt]);
        }
        // bias + stats
        float cb[8], cg[8], cB[8];
#pragma unroll
        for (int nt = 0; nt < 4; nt++)
#pragma unroll
            for (int c = 0; c < 2; c++) {
                int col = n0 + nt * 8 + qc * 2 + c;
                cb[nt * 2 + c] = b1[col]; cg[nt * 2 + c] = lg[col]; cB[nt * 2 + c] = lb[col];
            }
#pragma unroll
        for (int mt = 0; mt < 2; mt++)
#pragma unroll
            for (int h = 0; h < 2; h++) {
                float s = 0.f, q = 0.f;
#pragma unroll
                for (int nt = 0; nt < 4; nt++)
#pragma unroll
                    for (int c = 0; c < 2; c++) {
                        float v = acc[mt][nt][h * 2 + c] + cb[nt * 2 + c];
                        acc[mt][nt][h * 2 + c] = v;
                        s += v; q += v * v;
                    }
                s = quad_sum(s); q = quad_sum(q);
                if (qc == 0) {
                    int r = r0 + mt * 16 + qr + h * 8;
                    redS[r * 2 + wn] = s; redQ[r * 2 + wn] = q;
                }
            }
        __syncthreads();
#pragma unroll
        for (int mt = 0; mt < 2; mt++)
#pragma unroll
            for (int h = 0; h < 2; h++) {
                int r = r0 + mt * 16 + qr + h * 8;
                float s = redS[r * 2] + redS[r * 2 + 1];
                float q = redQ[r * 2] + redQ[r * 2 + 1];
                float mu = s * (1.f / 64.f);
                float rstd = rsqrtf(fmaxf(q * (1.f / 64.f) - mu * mu, 0.f) + EPS);
#pragma unroll
                for (int nt = 0; nt < 4; nt++)
#pragma unroll
                    for (int c = 0; c < 2; c++) {
                        float v = (acc[mt][nt][h * 2 + c] - mu) * rstd * cg[nt * 2 + c] + cB[nt * 2 + c];
                        v = v / (1.f + expf(-v));
                        As[r * SR + n0 + nt * 8 + qc * 2 + c] = tf32r(v);
                    }
            }
    }

    // ---- MMA2: 7 passes of N=128; warp tile 32 rows x 64 cols ----
    for (int p = 0; p < 7; p++) {
        __syncthreads();
        for (int idx = tid; idx < 8192; idx += 256) {
            int n = idx & 127, k = idx >> 7;
            Bs[n * SR + k] = tf32r(W2[(size_t)k * 896 + p * 128 + n]);
        }
        __syncthreads();
        float acc[2][8][4];
#pragma unroll
        for (int mt = 0; mt < 2; mt++)
#pragma unroll
            for (int nt = 0; nt < 8; nt++)
#pragma unroll
                for (int f = 0; f < 4; f++) acc[mt][nt][f] = 0.f;
#pragma unroll
        for (int ks = 0; ks < 8; ks++) {
            int k0 = ks * 8;
            uint32_t a[2][4], b[8][2];
            ldA(a[0], As, wm * 32, k0, qr, qc);
            ldA(a[1], As, wm * 32 + 16, k0, qr, qc);
#pragma unroll
            for (int nt = 0; nt < 8; nt++) ldB(b[nt], Bs, wn * 64 + nt * 8, k0, qr, qc);
#pragma unroll
            for (int mt = 0; mt < 2; mt++)
#pragma unroll
                for (int nt = 0; nt < 8; nt++) mma8(acc[mt][nt], a[mt], b[nt]);
        }
#pragma unroll
        for (int mt = 0; mt < 2; mt++)
#pragma unroll
            for (int h = 0; h < 2; h++) {
                int r = wm * 32 + mt * 16 + qr + h * 8, ge = e0 + r;
                if (ge < E) {
#pragma unroll
                    for (int nt = 0; nt < 8; nt++) {
                        int colg = p * 128 + wn * 64 + nt * 8 + qc * 2;
                        float2 v;
                        v.x = acc[mt][nt][h * 2] + roff[colg];
                        v.y = acc[mt][nt][h * 2 + 1] + roff[colg + 1];
                        *(float2*)&g_w[(size_t)ge * 896 + colg] = v;
                    }
                }
            }
    }
}

// ---------------------------------------------------------------------------
// F2: scalar path. 64 edges/block. A(64x384) built per 64-K chunk; N=256.
// Warps 2(M) x 4(N): warp tile 32 rows x 64 cols. Cross-warp LN via smem.
// ---------------------------------------------------------------------------
#define F2_SMEM ((64 * SR + 256 * SR + 256 + 512) * 4)
__global__ __launch_bounds__(256) void f2_s(
    const float* __restrict__ node, const float* __restrict__ eattr,
    const float* __restrict__ Ws, const float* __restrict__ bs,
    const float* __restrict__ gs, const float* __restrict__ gb,
    float* __restrict__ out, int E)
{
    extern __shared__ float sm[];
    float* As   = sm;                 // 64 x SR
    float* Bs   = As + 64 * SR;       // 256 x SR
    float* ysm  = Bs + 256 * SR;      // 64*4
    float* redS = ysm + 256;          // 64*4
    float* redQ = redS + 256;         // 64*4
    const int tid = threadIdx.x, wid = tid >> 5, lane = tid & 31;
    const int qr = lane >> 2, qc = lane & 3;
    const int e0 = blockIdx.x * 64;
    const int wm = wid & 1, wn = wid >> 1;

    {
        int ge = e0 + (tid >> 2);
        ysm[tid] = (ge < E) ? eattr[(size_t)ge * 4 + (tid & 3)] : 0.f;
    }

    float acc[2][8][4];
#pragma unroll
    for (int mt = 0; mt < 2; mt++)
#pragma unroll
        for (int nt = 0; nt < 8; nt++)
#pragma unroll
            for (int f = 0; f < 4; f++) acc[mt][nt][f] = 0.f;

    for (int q = 0; q < 6; q++) {
        __syncthreads();
        for (int idx = tid; idx < 4096; idx += 256) {
            int e = idx >> 6, kk = idx & 63, ge = e0 + e;
            float val = 0.f;
            if (ge < E) {
                if (q < 4) {
                    int u = q * 64 + kk;
                    val = node[(size_t)ge * 640 + u] * ysm[e * 4] * g_w[(size_t)ge * 896 + u];
                } else {
                    int j = (q - 4) * 64 + kk;
                    const float* xp = node + (size_t)ge * 640 + 256 + 3 * j;
                    float d = xp[0] * ysm[e * 4 + 1] + xp[1] * ysm[e * 4 + 2] +
                              xp[2] * ysm[e * 4 + 3];
                    val = S3 * d * g_w[(size_t)ge * 896 + 640 + j];
                }
            }
            As[e * SR + kk] = tf32r(val);
        }
        for (int idx = tid; idx < 16384; idx += 256) {
            int n = idx & 255, k = idx >> 8;
            Bs[n * SR + k] = tf32r(Ws[(size_t)(q * 64 + k) * 256 + n]);
        }
        __syncthreads();
#pragma unroll
        for (int ks = 0; ks < 8; ks++) {
            int k0 = ks * 8;
            uint32_t a[2][4], b[8][2];
            ldA(a[0], As, wm * 32, k0, qr, qc);
            ldA(a[1], As, wm * 32 + 16, k0, qr, qc);
#pragma unroll
            for (int nt = 0; nt < 8; nt++) ldB(b[nt], Bs, wn * 64 + nt * 8, k0, qr, qc);
#pragma unroll
            for (int mt = 0; mt < 2; mt++)
#pragma unroll
                for (int nt = 0; nt < 8; nt++) mma8(acc[mt][nt], a[mt], b[nt]);
        }
    }

    // ---- epilogue: +bias, LN over 256 cols (cross 4 N-warps), write ----
    float cb[16], cg[16], cB[16];
#pragma unroll
    for (int nt = 0; nt < 8; nt++)
#pragma unroll
        for (int c = 0; c < 2; c++) {
            int col = wn * 64 + nt * 8 + qc * 2 + c;
            cb[nt * 2 + c] = bs[col]; cg[nt * 2 + c] = gs[col]; cB[nt * 2 + c] = gb[col];
        }
#pragma unroll
    for (int mt = 0; mt < 2; mt++)
#pragma unroll
        for (int h = 0; h < 2; h++) {
            float s = 0.f, q = 0.f;
#pragma unroll
            for (int nt = 0; nt < 8; nt++)
#pragma unroll
                for (int c = 0; c < 2; c++) {
                    float v = acc[mt][nt][h * 2 + c] + cb[nt * 2 + c];
                    acc[mt][nt][h * 2 + c] = v;
                    s += v; q += v * v;
                }
            s = quad_sum(s); q = quad_sum(q);
            if (qc == 0) {
                int r = wm * 32 + mt * 16 + qr + h * 8;
                redS[r * 4 + wn] = s; redQ[r * 4 + wn] = q;
            }
        }
    __syncthreads();
#pragma unroll
    for (int mt = 0; mt < 2; mt++)
#pragma unroll
        for (int h = 0; h < 2; h++) {
            int r = wm * 32 + mt * 16 + qr + h * 8, ge = e0 + r;
            float s = redS[r * 4] + redS[r * 4 + 1] + redS[r * 4 + 2] + redS[r * 4 + 3];
            float q = redQ[r * 4] + redQ[r * 4 + 1] + redQ[r * 4 + 2] + redQ[r * 4 + 3];
            float mu = s * (1.f / 256.f);
            float rstd = rsqrtf(fmaxf(q * (1.f / 256.f) - mu * mu, 0.f) + EPS);
            if (ge < E) {
#pragma unroll
                for (int nt = 0; nt < 8; nt++) {
                    int col = wn * 64 + nt * 8 + qc * 2;
                    float2 v;
                    v.x = (acc[mt][nt][h * 2] - mu) * rstd * cg[nt * 2] + cB[nt * 2];
                    v.y = (acc[mt][nt][h * 2 + 1] - mu) * rstd * cg[nt * 2 + 1] + cB[nt * 2 + 1];
                    *(float2*)&out[(size_t)ge * 640 + col] = v;
                }
            }
        }
}

// ---------------------------------------------------------------------------
// F3: vector path. 64 edges/block. 3 GEMMs v_m = A_m(64x512) @ Wv.
//   u<256:      A_m = x0[u]*wB[u]*y1[m]
//   256..384:   A_m = x1[j][m]*y0*wC[j]
//   384..512:   A_m = S2*cross(x1[j],y1)[m]*wE[j]
// Warps 2(M) x 4(N): warp tile 32 rows x 32 cols, 3 planes (96 acc regs).
// ---------------------------------------------------------------------------
#define F3_SMEM ((3 * 64 * SR + 128 * SR + 256 + 256) * 4)
__global__ __launch_bounds__(256) void f3_v(
    const float* __restrict__ node, const float* __restrict__ eattr,
    const float* __restrict__ Wv, const float* __restrict__ gv,
    float* __restrict__ out, int E)
{
    extern __shared__ float sm[];
    float* A0  = sm;
    float* A1  = A0 + 64 * SR;
    float* A2  = A1 + 64 * SR;
    float* Bs  = A2 + 64 * SR;       // 128 x SR
    float* ysm = Bs + 128 * SR;      // 64*4
    float* redQ = ysm + 256;         // 64*4
    const int tid = threadIdx.x, wid = tid >> 5, lane = tid & 31;
    const int qr = lane >> 2, qc = lane & 3;
    const int e0 = blockIdx.x * 64;
    const int wm = wid & 1, wn = wid >> 1;
    const int r0 = wm * 32, n0 = wn * 32;

    {
        int ge = e0 + (tid >> 2);
        ysm[tid] = (ge < E) ? eattr[(size_t)ge * 4 + (tid & 3)] : 0.f;
    }

    float acc[3][2][4][4];
#pragma unroll
    for (int m = 0; m < 3; m++)
#pragma unroll
        for (int mt = 0; mt < 2; mt++)
#pragma unroll
            for (int nt = 0; nt < 4; nt++)
#pragma unroll
                for (int f = 0; f < 4; f++) acc[m][mt][nt][f] = 0.f;

    for (int q = 0; q < 8; q++) {
        __syncthreads();
        for (int idx = tid; idx < 4096; idx += 256) {
            int e = idx >> 6, kk = idx & 63, ge = e0 + e;
            float a0 = 0.f, a1 = 0.f, a2 = 0.f;
            if (ge < E) {
                float z0 = ysm[e * 4 + 1], z1 = ysm[e * 4 + 2], z2 = ysm[e * 4 + 3];
                if (q < 4) {
                    int u = q * 64 + kk;
                    float pr = node[(size_t)ge * 640 + u] * g_w[(size_t)ge * 896 + 256 + u];
                    a0 = pr * z0; a1 = pr * z1; a2 = pr * z2;
                } else if (q < 6) {
                    int j = (q - 4) * 64 + kk;
                    const float* xp = node + (size_t)ge * 640 + 256 + 3 * j;
                    float f = ysm[e * 4] * g_w[(size_t)ge * 896 + 512 + j];
                    a0 = xp[0] * f; a1 = xp[1] * f; a2 = xp[2] * f;
                } else {
                    int j = (q - 6) * 64 + kk;
                    const float* xp = node + (size_t)ge * 640 + 256 + 3 * j;
                    float x0v = xp[0], x1v = xp[1], x2v = xp[2];
                    float f = S2 * g_w[(size_t)ge * 896 + 768 + j];
                    a0 = (x1v * z2 - x2v * z1) * f;
                    a1 = (x2v * z0 - x0v * z2) * f;
                    a2 = (x0v * z1 - x1v * z0) * f;
                }
            }
            int o = e * SR + kk;
            A0[o] = tf32r(a0); A1[o] = tf32r(a1); A2[o] = tf32r(a2);
        }
        for (int idx = tid; idx < 8192; idx += 256) {
            int n = idx & 127, k = idx >> 7;
            Bs[n * SR + k] = tf32r(Wv[(size_t)(q * 64 + k) * 128 + n]);
        }
        __syncthreads();
#pragma unroll
        for (int ks = 0; ks < 8; ks++) {
            int k0 = ks * 8;
            uint32_t b[4][2];
#pragma unroll
            for (int nt = 0; nt < 4; nt++) ldB(b[nt], Bs, n0 + nt * 8, k0, qr, qc);
            const float* Ap[3] = {A0, A1, A2};
#pragma unroll
            for (int m = 0; m < 3; m++) {
                uint32_t a[2][4];
                ldA(a[0], Ap[m], r0, k0, qr, qc);
                ldA(a[1], Ap[m], r0 + 16, k0, qr, qc);
#pragma unroll
                for (int mt = 0; mt < 2; mt++)
#pragma unroll
                    for (int nt = 0; nt < 4; nt++) mma8(acc[m][mt][nt], a[mt], b[nt]);
            }
        }
    }

    // ---- epilogue: sumsq over 3 planes x 128 cols per row, norm, write ----
#pragma unroll
    for (int mt = 0; mt < 2; mt++)
#pragma unroll
        for (int h = 0; h < 2; h++) {
            float q = 0.f;
#pragma unroll
            for (int m = 0; m < 3; m++)
#pragma unroll
                for (int nt = 0; nt < 4; nt++)
#pragma unroll
                    for (int c = 0; c < 2; c++) {
                        float v = acc[m][mt][nt][h * 2 + c];
                        q += v * v;
                    }
            q = quad_sum(q);
            if (qc == 0) {
                int r = r0 + mt * 16 + qr + h * 8;
                redQ[r * 4 + wn] = q;
            }
        }
    __syncthreads();
    float cg[8];
#pragma unroll
    for (int nt = 0; nt < 4; nt++)
#pragma unroll
        for (int c = 0; c < 2; c++) cg[nt * 2 + c] = gv[n0 + nt * 8 + qc * 2 + c];
#pragma unroll
    for (int mt = 0; mt < 2; mt++)
#pragma unroll
        for (int h = 0; h < 2; h++) {
            int r = r0 + mt * 16 + qr + h * 8, ge = e0 + r;
            float qt = redQ[r * 4] + redQ[r * 4 + 1] + redQ[r * 4 + 2] + redQ[r * 4 + 3];
            float rstd = rsqrtf(qt * (1.f / 384.f) + EPS);
            if (ge < E) {
                float* ob = out + (size_t)ge * 640 + 256;
#pragma unroll
                for (int nt = 0; nt < 4; nt++)
#pragma unroll
                    for (int c = 0; c < 2; c++) {
                        int col = n0 + nt * 8 + qc * 2 + c;
                        float g = cg[nt * 2 + c] * rstd;
                        ob[3 * col + 0] = acc[0][mt][nt][h * 2 + c] * g;
                        ob[3 * col + 1] = acc[1][mt][nt][h * 2 + c] * g;
                        ob[3 * col + 2] = acc[2][mt][nt][h * 2 + c] * g;
                    }
            }
        }
}

// ---------------------------------------------------------------------------
extern "C" void kernel_launch(void* const* d_in, const int* in_sizes, int n_in,
                              void* d_out, int out_size)
{
    const float* node  = (const float*)d_in[0];   // (E, 640)
    const float* eattr = (const float*)d_in[1];   // (E, 4)
    const float* escal = (const float*)d_in[2];   // (E, 64)
    const float* rW1   = (const float*)d_in[3];   // (64, 64)
    const float* rb1   = (const float*)d_in[4];   // (64,)
    const float* rlg   = (const float*)d_in[5];   // (64,)
    const float* rlb   = (const float*)d_in[6];   // (64,)
    const float* rW2   = (const float*)d_in[7];   // (64, 896)
    const float* roff  = (const float*)d_in[8];   // (896,)
    const float* Ws    = (const float*)d_in[9];   // (384, 256)
    const float* bs    = (const float*)d_in[10];  // (256,)
    const float* Wv    = (const float*)d_in[11];  // (512, 128)
    const float* gs    = (const float*)d_in[12];  // (256,)
    const float* gb    = (const float*)d_in[13];  // (256,)
    const float* gv    = (const float*)d_in[14];  // (128,)
    float* out = (float*)d_out;

    const int E = in_sizes[1] / 4;
    const int nb128 = (E + 127) / 128;
    const int nb64  = (E + 63) / 64;

    cudaFuncSetAttribute(f1_kw, cudaFuncAttributeMaxDynamicSharedMemorySize, F1_SMEM);
    cudaFuncSetAttribute(f2_s,  cudaFuncAttributeMaxDynamicSharedMemorySize, F2_SMEM);
    cudaFuncSetAttribute(f3_v,  cudaFuncAttributeMaxDynamicSharedMemorySize, F3_SMEM);

    f1_kw<<<nb128, 256, F1_SMEM>>>(escal, rW1, rb1, rlg, rlb, rW2, roff, E);
    f2_s<<<nb64, 256, F2_SMEM>>>(node, eattr, Ws, bs, gs, gb, out, E);
    f3_v<<<nb64, 256, F3_SMEM>>>(node, eattr, Wv, gv, out, E);
}

// round 9
// speedup vs baseline: 1.9431x; 1.0587x over previous
#include <cuda_runtime.h>
#include <math.h>
#include <stdint.h>

#define S3 0.5773502691896258f
#define S2 0.7071067811865476f
#define EPS 1e-5f

// per-edge TP weights scratch (static device global: allowed)
__device__ float g_w[(size_t)100000 * 896];

__device__ __forceinline__ float tf32r(float x) {
    uint32_t u;
    asm("cvt.rna.tf32.f32 %0, %1;" : "=r"(u) : "f"(x));
    return __uint_as_float(u);
}

// mma.sync m16n8k8 tf32: D += A(16x8) * B(8x8)^T, fp32 accum (baseline PTX, sm_80+)
__device__ __forceinline__ void mma8(float d[4], const uint32_t a[4], const uint32_t b[2]) {
    asm volatile(
        "mma.sync.aligned.m16n8k8.row.col.f32.tf32.tf32.f32 "
        "{%0,%1,%2,%3}, {%4,%5,%6,%7}, {%8,%9}, {%0,%1,%2,%3};"
        : "+f"(d[0]), "+f"(d[1]), "+f"(d[2]), "+f"(d[3])
        : "r"(a[0]), "r"(a[1]), "r"(a[2]), "r"(a[3]), "r"(b[0]), "r"(b[1]));
}
// Packed A tile: quad (mt,ks,lane) holds [(r,k),(r,k+4),(r+8,k),(r+8,k+4)],
// r = mt*16 + lane/4, k = ks*8 + lane%4.  One LDS.128 per fragment.
__device__ __forceinline__ void ldApk(uint32_t a[4], const float4* Ap, int mt, int ks, int lane) {
    float4 v = Ap[(mt * 8 + ks) * 32 + lane];
    a[0] = __float_as_uint(v.x);   // (r,   k)
    a[1] = __float_as_uint(v.z);   // (r+8, k)
    a[2] = __float_as_uint(v.y);   // (r,   k+4)
    a[3] = __float_as_uint(v.w);   // (r+8, k+4)
}
// Packed B tile: float2 quad (ng,ks,lane) holds [B(n,k), B(n,k+4)],
// n = ng*8 + lane/4, k = ks*8 + lane%4.  One LDS.64 per fragment.
__device__ __forceinline__ void ldBpk(uint32_t b[2], const float2* Bp, int ng, int ks, int lane) {
    float2 v = Bp[(ng * 8 + ks) * 32 + lane];
    b[0] = __float_as_uint(v.x);
    b[1] = __float_as_uint(v.y);
}
__device__ __forceinline__ float quad_sum(float v) {
    v += __shfl_xor_sync(0xffffffffu, v, 1);
    v += __shfl_xor_sync(0xffffffffu, v, 2);
    return v;
}

// ---------------------------------------------------------------------------
// F1: fused rad-MLP. 128 edges/block, 8 warps (wm 0..3 x wn 0..1).
//   MMA1: hraw = es@W1 (M128,N64,K64); epi: h = silu(LN(hraw+b1)) -> packed A
//   7 passes: g_w[:, p*128..+128] = h@W2 + roff
// ---------------------------------------------------------------------------
#define F1_SMEM ((8192 + 8192 + 512) * 4)
__global__ __launch_bounds__(256, 2) void f1_kw(
    const float* __restrict__ es, const float* __restrict__ W1,
    const float* __restrict__ b1, const float* __restrict__ lg,
    const float* __restrict__ lb, const float* __restrict__ W2,
    const float* __restrict__ roff, int E)
{
    extern __shared__ float sm[];
    float4* As4 = (float4*)sm;              // 2048 quads (128 x 64)
    float2* Bp  = (float2*)(sm + 8192);     // 4096 float2 quads
    float* redS = sm + 16384;               // 256
    float* redQ = redS + 256;               // 256
    const int tid = threadIdx.x, wid = tid >> 5, lane = tid & 31;
    const int qr = lane >> 2, qc = lane & 3;
    const int e0 = blockIdx.x * 128;
    const int wm = wid & 3, wn = wid >> 2;

    // packed es tile
    for (int qd = tid; qd < 2048; qd += 256) {
        int mt = qd >> 8, kg = (qd >> 5) & 7, ln = qd & 31;
        int ea = e0 + mt * 16 + (ln >> 2), ka = kg * 8 + (ln & 3);
        int eb = ea + 8;
        float v00 = (ea < E) ? es[(size_t)ea * 64 + ka] : 0.f;
        float v01 = (ea < E) ? es[(size_t)ea * 64 + ka + 4] : 0.f;
        float v10 = (eb < E) ? es[(size_t)eb * 64 + ka] : 0.f;
        float v11 = (eb < E) ? es[(size_t)eb * 64 + ka + 4] : 0.f;
        As4[qd] = make_float4(tf32r(v00), tf32r(v01), tf32r(v10), tf32r(v11));
    }
    // packed W1 (N=64): 2048 quads
    for (int qd = tid; qd < 2048; qd += 256) {
        int ng = qd >> 8, ks = (qd >> 5) & 7, ln = qd & 31;
        int n = ng * 8 + (ln >> 2), k = ks * 8 + (ln & 3);
        Bp[qd] = make_float2(tf32r(W1[k * 64 + n]), tf32r(W1[(k + 4) * 64 + n]));
    }
    __syncthreads();

    {   // ---- MMA1: warp tile 32 rows x 32 cols ----
        const int n0 = wn * 32;
        float acc[2][4][4];
#pragma unroll
        for (int mt = 0; mt < 2; mt++)
#pragma unroll
            for (int nt = 0; nt < 4; nt++)
#pragma unroll
                for (int f = 0; f < 4; f++) acc[mt][nt][f] = 0.f;
#pragma unroll
        for (int ks = 0; ks < 8; ks++) {
            uint32_t a[2][4];
            ldApk(a[0], As4, wm * 2, ks, lane);
            ldApk(a[1], As4, wm * 2 + 1, ks, lane);
#pragma unroll
            for (int nt = 0; nt < 4; nt++) {
                uint32_t b[2];
                ldBpk(b, Bp, wn * 4 + nt, ks, lane);
                mma8(acc[0][nt], a[0], b);
                mma8(acc[1][nt], a[1], b);
            }
        }
        // bias + stats + LN + silu -> write h into packed A tile
        float cb[8], cg[8], cB[8];
#pragma unroll
        for (int nt = 0; nt < 4; nt++)
#pragma unroll
            for (int c = 0; c < 2; c++) {
                int col = n0 + nt * 8 + qc * 2 + c;
                cb[nt * 2 + c] = b1[col]; cg[nt * 2 + c] = lg[col]; cB[nt * 2 + c] = lb[col];
            }
#pragma unroll
        for (int mt = 0; mt < 2; mt++)
#pragma unroll
            for (int h = 0; h < 2; h++) {
                float s = 0.f, q = 0.f;
#pragma unroll
                for (int nt = 0; nt < 4; nt++)
#pragma unroll
                    for (int c = 0; c < 2; c++) {
                        float v = acc[mt][nt][h * 2 + c] + cb[nt * 2 + c];
                        acc[mt][nt][h * 2 + c] = v;
                        s += v; q += v * v;
                    }
                s = quad_sum(s); q = quad_sum(q);
                if (qc == 0) {
                    int r = wm * 32 + mt * 16 + qr + h * 8;
                    redS[r * 2 + wn] = s; redQ[r * 2 + wn] = q;
                }
            }
        __syncthreads();
#pragma unroll
        for (int mt = 0; mt < 2; mt++)
#pragma unroll
            for (int h = 0; h < 2; h++) {
                int r = wm * 32 + mt * 16 + qr + h * 8;
                float s = redS[r * 2] + redS[r * 2 + 1];
                float q = redQ[r * 2] + redQ[r * 2 + 1];
                float mu = s * (1.f / 64.f);
                float rstd = rsqrtf(fmaxf(q * (1.f / 64.f) - mu * mu, 0.f) + EPS);
                int mtp = wm * 2 + mt;
#pragma unroll
                for (int nt = 0; nt < 4; nt++)
#pragma unroll
                    for (int c = 0; c < 2; c++) {
                        float v = (acc[mt][nt][h * 2 + c] - mu) * rstd * cg[nt * 2 + c] + cB[nt * 2 + c];
                        v = v / (1.f + expf(-v));
                        int col = n0 + nt * 8 + qc * 2 + c;
                        int word = ((mtp * 8 + (col >> 3)) * 32 + qr * 4 + (col & 3)) * 4
                                   + h * 2 + ((col >> 2) & 1);
                        sm[word] = tf32r(v);
                    }
            }
    }

    // ---- MMA2: 7 passes of N=128; warp tile 32 rows x 64 cols ----
    for (int p = 0; p < 7; p++) {
        __syncthreads();
        for (int qd = tid; qd < 4096; qd += 256) {
            int ng = qd >> 8, ks = (qd >> 5) & 7, ln = qd & 31;
            int n = p * 128 + ng * 8 + (ln >> 2), k = ks * 8 + (ln & 3);
            Bp[qd] = make_float2(tf32r(W2[(size_t)k * 896 + n]),
                                 tf32r(W2[(size_t)(k + 4) * 896 + n]));
        }
        __syncthreads();
        float acc[2][8][4];
#pragma unroll
        for (int mt = 0; mt < 2; mt++)
#pragma unroll
            for (int nt = 0; nt < 8; nt++)
#pragma unroll
                for (int f = 0; f < 4; f++) acc[mt][nt][f] = 0.f;
#pragma unroll
        for (int ks = 0; ks < 8; ks++) {
            uint32_t a[2][4];
            ldApk(a[0], As4, wm * 2, ks, lane);
            ldApk(a[1], As4, wm * 2 + 1, ks, lane);
#pragma unroll
            for (int nt = 0; nt < 8; nt++) {
                uint32_t b[2];
                ldBpk(b, Bp, wn * 8 + nt, ks, lane);
                mma8(acc[0][nt], a[0], b);
                mma8(acc[1][nt], a[1], b);
            }
        }
#pragma unroll
        for (int mt = 0; mt < 2; mt++)
#pragma unroll
            for (int h = 0; h < 2; h++) {
                int r = wm * 32 + mt * 16 + qr + h * 8, ge = e0 + r;
                if (ge < E) {
#pragma unroll
                    for (int nt = 0; nt < 8; nt++) {
                        int colg = p * 128 + wn * 64 + nt * 8 + qc * 2;
                        float2 v;
                        v.x = acc[mt][nt][h * 2] + roff[colg];
                        v.y = acc[mt][nt][h * 2 + 1] + roff[colg + 1];
                        *(float2*)&g_w[(size_t)ge * 896 + colg] = v;
                    }
                }
            }
    }
}

// ---------------------------------------------------------------------------
// F2: scalar path. 64 edges/block (wm 0..1 x wn 0..3). A(64x384) per 64-K chunk.
// ---------------------------------------------------------------------------
__device__ __forceinline__ float f2_val(
    const float* __restrict__ node, const float* __restrict__ ysm,
    int e0, int E, int q, int e, int kk)
{
    int ge = e0 + e;
    if (ge >= E) return 0.f;
    if (q < 4) {
        int u = q * 64 + kk;
        return node[(size_t)ge * 640 + u] * ysm[e * 4] * g_w[(size_t)ge * 896 + u];
    } else {
        int j = (q - 4) * 64 + kk;
        const float* xp = node + (size_t)ge * 640 + 256 + 3 * j;
        float d = xp[0] * ysm[e * 4 + 1] + xp[1] * ysm[e * 4 + 2] + xp[2] * ysm[e * 4 + 3];
        return S3 * d * g_w[(size_t)ge * 896 + 640 + j];
    }
}

#define F2_SMEM ((4096 + 16384 + 256 + 512) * 4)
__global__ __launch_bounds__(256, 2) void f2_s(
    const float* __restrict__ node, const float* __restrict__ eattr,
    const float* __restrict__ Ws, const float* __restrict__ bs,
    const float* __restrict__ gs, const float* __restrict__ gb,
    float* __restrict__ out, int E)
{
    extern __shared__ float sm[];
    float4* As4 = (float4*)sm;              // 1024 quads (64 x 64)
    float2* Bp  = (float2*)(sm + 4096);     // 8192 float2 quads (N=256)
    float* ysm  = sm + 4096 + 16384;        // 256
    float* redS = ysm + 256;                // 256
    float* redQ = redS + 256;               // 256
    const int tid = threadIdx.x, wid = tid >> 5, lane = tid & 31;
    const int qr = lane >> 2, qc = lane & 3;
    const int e0 = blockIdx.x * 64;
    const int wm = wid & 1, wn = wid >> 1;

    {
        int ge = e0 + (tid >> 2);
        ysm[tid] = (ge < E) ? eattr[(size_t)ge * 4 + (tid & 3)] : 0.f;
    }

    float acc[2][8][4];
#pragma unroll
    for (int mt = 0; mt < 2; mt++)
#pragma unroll
        for (int nt = 0; nt < 8; nt++)
#pragma unroll
            for (int f = 0; f < 4; f++) acc[mt][nt][f] = 0.f;

    for (int q = 0; q < 6; q++) {
        __syncthreads();
        for (int qd = tid; qd < 1024; qd += 256) {
            int mt = qd >> 8, kg = (qd >> 5) & 7, ln = qd & 31;
            int ea = mt * 16 + (ln >> 2), ka = kg * 8 + (ln & 3);
            float v00 = f2_val(node, ysm, e0, E, q, ea, ka);
            float v01 = f2_val(node, ysm, e0, E, q, ea, ka + 4);
            float v10 = f2_val(node, ysm, e0, E, q, ea + 8, ka);
            float v11 = f2_val(node, ysm, e0, E, q, ea + 8, ka + 4);
            As4[qd] = make_float4(tf32r(v00), tf32r(v01), tf32r(v10), tf32r(v11));
        }
        for (int qd = tid; qd < 8192; qd += 256) {
            int ng = qd >> 8, ks = (qd >> 5) & 7, ln = qd & 31;
            int n = ng * 8 + (ln >> 2), k = q * 64 + ks * 8 + (ln & 3);
            Bp[qd] = make_float2(tf32r(Ws[(size_t)k * 256 + n]),
                                 tf32r(Ws[(size_t)(k + 4) * 256 + n]));
        }
        __syncthreads();
#pragma unroll
        for (int ks = 0; ks < 8; ks++) {
            uint32_t a[2][4];
            ldApk(a[0], As4, wm * 2, ks, lane);
            ldApk(a[1], As4, wm * 2 + 1, ks, lane);
#pragma unroll
            for (int nt = 0; nt < 8; nt++) {
                uint32_t b[2];
                ldBpk(b, Bp, wn * 8 + nt, ks, lane);
                mma8(acc[0][nt], a[0], b);
                mma8(acc[1][nt], a[1], b);
            }
        }
    }

    // ---- epilogue: +bias, LN over 256 cols (cross 4 N-warps), write ----
    float cb[16], cg[16], cB[16];
#pragma unroll
    for (int nt = 0; nt < 8; nt++)
#pragma unroll
        for (int c = 0; c < 2; c++) {
            int col = wn * 64 + nt * 8 + qc * 2 + c;
            cb[nt * 2 + c] = bs[col]; cg[nt * 2 + c] = gs[col]; cB[nt * 2 + c] = gb[col];
        }
#pragma unroll
    for (int mt = 0; mt < 2; mt++)
#pragma unroll
        for (int h = 0; h < 2; h++) {
            float s = 0.f, q = 0.f;
#pragma unroll
            for (int nt = 0; nt < 8; nt++)
#pragma unroll
                for (int c = 0; c < 2; c++) {
                    float v = acc[mt][nt][h * 2 + c] + cb[nt * 2 + c];
                    acc[mt][nt][h * 2 + c] = v;
                    s += v; q += v * v;
                }
            s = quad_sum(s); q = quad_sum(q);
            if (qc == 0) {
                int r = wm * 32 + mt * 16 + qr + h * 8;
                redS[r * 4 + wn] = s; redQ[r * 4 + wn] = q;
            }
        }
    __syncthreads();
#pragma unroll
    for (int mt = 0; mt < 2; mt++)
#pragma unroll
        for (int h = 0; h < 2; h++) {
            int r = wm * 32 + mt * 16 + qr + h * 8, ge = e0 + r;
            float s = redS[r * 4] + redS[r * 4 + 1] + redS[r * 4 + 2] + redS[r * 4 + 3];
            float q = redQ[r * 4] + redQ[r * 4 + 1] + redQ[r * 4 + 2] + redQ[r * 4 + 3];
            float mu = s * (1.f / 256.f);
            float rstd = rsqrtf(fmaxf(q * (1.f / 256.f) - mu * mu, 0.f) + EPS);
            if (ge < E) {
#pragma unroll
                for (int nt = 0; nt < 8; nt++) {
                    int col = wn * 64 + nt * 8 + qc * 2;
                    float2 v;
                    v.x = (acc[mt][nt][h * 2] - mu) * rstd * cg[nt * 2] + cB[nt * 2];
                    v.y = (acc[mt][nt][h * 2 + 1] - mu) * rstd * cg[nt * 2 + 1] + cB[nt * 2 + 1];
                    *(float2*)&out[(size_t)ge * 640 + col] = v;
                }
            }
        }
}

// ---------------------------------------------------------------------------
// F3: vector path, 4-plane formulation (1/3 less MMA work than 3 full GEMMs):
//   plane R (q<4):  Ra = sum_{u<256} Wv[u,k] * x0[u]*wB[u]
//   planes m (q>=4): acc_m = sum_j Wv[256+j,k]*x1[j][m]*y0*wC[j]
//                         + sum_j Wv[384+j,k]*S2*cross(x1[j],y1)[m]*wE[j]
//   v_m = y1[m]*Ra + acc_m; norm over 384; write interleaved.
// 64 edges/block, 512 threads (wm 0..1 x wn 0..7, warp tile 32 x 16).
// ---------------------------------------------------------------------------
#define F3_SMEM ((12288 + 8192 + 256 + 512) * 4)
__global__ __launch_bounds__(512, 1) void f3_v(
    const float* __restrict__ node, const float* __restrict__ eattr,
    const float* __restrict__ Wv, const float* __restrict__ gv,
    float* __restrict__ out, int E)
{
    extern __shared__ float sm[];
    float4* A04 = (float4*)sm;                  // 1024 quads each
    float4* A14 = A04 + 1024;
    float4* A24 = A14 + 1024;
    float2* Bp  = (float2*)(sm + 12288);        // 4096 float2 quads (N=128)
    float* ysm  = sm + 12288 + 8192;            // 256
    float* redQ = ysm + 256;                    // 512
    const int tid = threadIdx.x, wid = tid >> 5, lane = tid & 31;
    const int qr = lane >> 2, qc = lane & 3;
    const int e0 = blockIdx.x * 64;
    const int wm = wid & 1, wn = wid >> 1;      // wn 0..7
    const int n0 = wn * 16;

    if (tid < 256) {
        int ge = e0 + (tid >> 2);
        ysm[tid] = (ge < E) ? eattr[(size_t)ge * 4 + (tid & 3)] : 0.f;
    }

    float accR[2][2][4];        // plane R: 2 mt x 2 nt
    float accM[3][2][2][4];     // planes m
#pragma unroll
    for (int mt = 0; mt < 2; mt++)
#pragma unroll
        for (int nt = 0; nt < 2; nt++)
#pragma unroll
            for (int f = 0; f < 4; f++) {
                accR[mt][nt][f] = 0.f;
#pragma unroll
                for (int m = 0; m < 3; m++) accM[m][mt][nt][f] = 0.f;
            }

    for (int q = 0; q < 8; q++) {
        __syncthreads();
        if (q < 4) {
            // A0 = pr = x0*wB (no y factor)
            for (int qd = tid; qd < 1024; qd += 512) {
                int mt = qd >> 8, kg = (qd >> 5) & 7, ln = qd & 31;
                int ea = mt * 16 + (ln >> 2), ka = kg * 8 + (ln & 3);
                float v[4];
#pragma unroll
                for (int t = 0; t < 4; t++) {
                    int e = ea + (t >> 1) * 8, kk = ka + (t & 1) * 4;
                    int ge = e0 + e;
                    int u = q * 64 + kk;
                    v[t] = (ge < E)
                         ? node[(size_t)ge * 640 + u] * g_w[(size_t)ge * 896 + 256 + u]
                         : 0.f;
                }
                A04[qd] = make_float4(tf32r(v[0]), tf32r(v[1]), tf32r(v[2]), tf32r(v[3]));
            }
        } else {
            for (int qd = tid; qd < 1024; qd += 512) {
                int mt = qd >> 8, kg = (qd >> 5) & 7, ln = qd & 31;
                int ea = mt * 16 + (ln >> 2), ka = kg * 8 + (ln & 3);
                float a0[4], a1[4], a2[4];
#pragma unroll
                for (int t = 0; t < 4; t++) {
                    int e = ea + (t >> 1) * 8, kk = ka + (t & 1) * 4;
                    int ge = e0 + e;
                    a0[t] = a1[t] = a2[t] = 0.f;
                    if (ge < E) {
                        if (q < 6) {
                            int j = (q - 4) * 64 + kk;
                            const float* xp = node + (size_t)ge * 640 + 256 + 3 * j;
                            float f = ysm[e * 4] * g_w[(size_t)ge * 896 + 512 + j];
                            a0[t] = xp[0] * f; a1[t] = xp[1] * f; a2[t] = xp[2] * f;
                        } else {
                            int j = (q - 6) * 64 + kk;
                            const float* xp = node + (size_t)ge * 640 + 256 + 3 * j;
                            float x0v = xp[0], x1v = xp[1], x2v = xp[2];
                            float z0 = ysm[e * 4 + 1], z1 = ysm[e * 4 + 2], z2 = ysm[e * 4 + 3];
                            float f = S2 * g_w[(size_t)ge * 896 + 768 + j];
                            a0[t] = (x1v * z2 - x2v * z1) * f;
                            a1[t] = (x2v * z0 - x0v * z2) * f;
                            a2[t] = (x0v * z1 - x1v * z0) * f;
                        }
                    }
                }
                A04[qd] = make_float4(tf32r(a0[0]), tf32r(a0[1]), tf32r(a0[2]), tf32r(a0[3]));
                A14[qd] = make_float4(tf32r(a1[0]), tf32r(a1[1]), tf32r(a1[2]), tf32r(a1[3]));
                A24[qd] = make_float4(tf32r(a2[0]), tf32r(a2[1]), tf32r(a2[2]), tf32r(a2[3]));
            }
        }
        // packed Wv chunk (N=128)
        for (int qd = tid; qd < 4096; qd += 512) {
            int ng = qd >> 8, ks = (qd >> 5) & 7, ln = qd & 31;
            int n = ng * 8 + (ln >> 2), k = q * 64 + ks * 8 + (ln & 3);
            Bp[qd] = make_float2(tf32r(Wv[(size_t)k * 128 + n]),
                                 tf32r(Wv[(size_t)(k + 4) * 128 + n]));
        }
        __syncthreads();

        if (q < 4) {
#pragma unroll
            for (int ks = 0; ks < 8; ks++) {
                uint32_t a[2][4];
                ldApk(a[0], A04, wm * 2, ks, lane);
                ldApk(a[1], A04, wm * 2 + 1, ks, lane);
#pragma unroll
                for (int nt = 0; nt < 2; nt++) {
                    uint32_t b[2];
                    ldBpk(b, Bp, wn * 2 + nt, ks, lane);
                    mma8(accR[0][nt], a[0], b);
                    mma8(accR[1][nt], a[1], b);
                }
            }
        } else {
#pragma unroll
            for (int ks = 0; ks < 8; ks++) {
                uint32_t b[2][2];
#pragma unroll
                for (int nt = 0; nt < 2; nt++) ldBpk(b[nt], Bp, wn * 2 + nt, ks, lane);
                const float4* Ap[3] = {A04, A14, A24};
#pragma unroll
                for (int m = 0; m < 3; m++) {
                    uint32_t a[2][4];
                    ldApk(a[0], Ap[m], wm * 2, ks, lane);
                    ldApk(a[1], Ap[m], wm * 2 + 1, ks, lane);
#pragma unroll
                    for (int nt = 0; nt < 2; nt++) {
                        mma8(accM[m][0][nt], a[0], b[nt]);
                        mma8(accM[m][1][nt], a[1], b[nt]);
                    }
                }
            }
        }
    }

    // ---- epilogue: fold R plane, sumsq, norm, write ----
#pragma unroll
    for (int mt = 0; mt < 2; mt++)
#pragma unroll
        for (int h = 0; h < 2; h++) {
            int e = wm * 32 + mt * 16 + qr + h * 8;
            float z0 = ysm[e * 4 + 1], z1 = ysm[e * 4 + 2], z2 = ysm[e * 4 + 3];
            float s = 0.f;
#pragma unroll
            for (int nt = 0; nt < 2; nt++)
#pragma unroll
                for (int c = 0; c < 2; c++) {
                    float R = accR[mt][nt][h * 2 + c];
                    float v0 = z0 * R + accM[0][mt][nt][h * 2 + c];
                    float v1 = z1 * R + accM[1][mt][nt][h * 2 + c];
                    float v2 = z2 * R + accM[2][mt][nt][h * 2 + c];
                    accM[0][mt][nt][h * 2 + c] = v0;
                    accM[1][mt][nt][h * 2 + c] = v1;
                    accM[2][mt][nt][h * 2 + c] = v2;
                    s += v0 * v0 + v1 * v1 + v2 * v2;
                }
            s = quad_sum(s);
            if (qc == 0) redQ[e * 8 + wn] = s;
        }
    __syncthreads();
    float cg[4];
#pragma unroll
    for (int nt = 0; nt < 2; nt++)
#pragma unroll
        for (int c = 0; c < 2; c++) cg[nt * 2 + c] = gv[n0 + nt * 8 + qc * 2 + c];
#pragma unroll
    for (int mt = 0; mt < 2; mt++)
#pragma unroll
        for (int h = 0; h < 2; h++) {
            int e = wm * 32 + mt * 16 + qr + h * 8, ge = e0 + e;
            float qt = 0.f;
#pragma unroll
            for (int w8 = 0; w8 < 8; w8++) qt += redQ[e * 8 + w8];
            float rstd = rsqrtf(qt * (1.f / 384.f) + EPS);
            if (ge < E) {
                float* ob = out + (size_t)ge * 640 + 256;
#pragma unroll
                for (int nt = 0; nt < 2; nt++)
#pragma unroll
                    for (int c = 0; c < 2; c++) {
                        int col = n0 + nt * 8 + qc * 2 + c;
                        float g = cg[nt * 2 + c] * rstd;
                        ob[3 * col + 0] = accM[0][mt][nt][h * 2 + c] * g;
                        ob[3 * col + 1] = accM[1][mt][nt][h * 2 + c] * g;
                        ob[3 * col + 2] = accM[2][mt][nt][h * 2 + c] * g;
                    }
            }
        }
}

// ---------------------------------------------------------------------------
extern "C" void kernel_launch(void* const* d_in, const int* in_sizes, int n_in,
                              void* d_out, int out_size)
{
    const float* node  = (const float*)d_in[0];   // (E, 640)
    const float* eattr = (const float*)d_in[1];   // (E, 4)
    const float* escal = (const float*)d_in[2];   // (E, 64)
    const float* rW1   = (const float*)d_in[3];   // (64, 64)
    const float* rb1   = (const float*)d_in[4];   // (64,)
    const float* rlg   = (const float*)d_in[5];   // (64,)
    const float* rlb   = (const float*)d_in[6];   // (64,)
    const float* rW2   = (const float*)d_in[7];   // (64, 896)
    const float* roff  = (const float*)d_in[8];   // (896,)
    const float* Ws    = (const float*)d_in[9];   // (384, 256)
    const float* bs    = (const float*)d_in[10];  // (256,)
    const float* Wv    = (const float*)d_in[11];  // (512, 128)
    const float* gs    = (const float*)d_in[12];  // (256,)
    const float* gb    = (const float*)d_in[13];  // (256,)
    const float* gv    = (const float*)d_in[14];  // (128,)
    float* out = (float*)d_out;

    const int E = in_sizes[1] / 4;
    const int nb128 = (E + 127) / 128;
    const int nb64  = (E + 63) / 64;

    cudaFuncSetAttribute(f1_kw, cudaFuncAttributeMaxDynamicSharedMemorySize, F1_SMEM);
    cudaFuncSetAttribute(f2_s,  cudaFuncAttributeMaxDynamicSharedMemorySize, F2_SMEM);
    cudaFuncSetAttribute(f3_v,  cudaFuncAttributeMaxDynamicSharedMemorySize, F3_SMEM);

    f1_kw<<<nb128, 256, F1_SMEM>>>(escal, rW1, rb1, rlg, rlb, rW2, roff, E);
    f2_s<<<nb64, 256, F2_SMEM>>>(node, eattr, Ws, bs, gs, gb, out, E);
    f3_v<<<nb64, 512, F3_SMEM>>>(node, eattr, Wv, gv, out, E);
}

// round 10
// speedup vs baseline: 2.3376x; 1.2031x over previous
#include <cuda_runtime.h>
#include <math.h>
#include <stdint.h>

#define S3 0.5773502691896258f
#define S2 0.7071067811865476f
#define EPS 1e-5f

// per-edge TP weights scratch (static device global: allowed)
__device__ float g_w[(size_t)100000 * 896];
// pre-rounded (tf32 rna) weights: W1[4096] | W2[57344] | Ws[98304] | Wv[65536]
__device__ float g_wr[225280];
#define W1R_OFF 0
#define W2R_OFF 4096
#define WSR_OFF 61440
#define WVR_OFF 159744

__device__ __forceinline__ float tf32r(float x) {
    uint32_t u;
    asm("cvt.rna.tf32.f32 %0, %1;" : "=r"(u) : "f"(x));
    return __uint_as_float(u);
}

// mma.sync m16n8k8 tf32: D += A(16x8) * B(8x8)^T, fp32 accum (baseline PTX, sm_80+)
__device__ __forceinline__ void mma8(float d[4], const uint32_t a[4], const uint32_t b[2]) {
    asm volatile(
        "mma.sync.aligned.m16n8k8.row.col.f32.tf32.tf32.f32 "
        "{%0,%1,%2,%3}, {%4,%5,%6,%7}, {%8,%9}, {%0,%1,%2,%3};"
        : "+f"(d[0]), "+f"(d[1]), "+f"(d[2]), "+f"(d[3])
        : "r"(a[0]), "r"(a[1]), "r"(a[2]), "r"(a[3]), "r"(b[0]), "r"(b[1]));
}
// Packed A tile: quad (mt,ks,lane) holds [(r,k),(r,k+4),(r+8,k),(r+8,k+4)],
// r = mt*16 + lane/4, k = ks*8 + lane%4.  One LDS.128 per fragment.
__device__ __forceinline__ void ldApk(uint32_t a[4], const float4* Ap, int mt, int ks, int lane) {
    float4 v = Ap[(mt * 8 + ks) * 32 + lane];
    a[0] = __float_as_uint(v.x);
    a[1] = __float_as_uint(v.z);
    a[2] = __float_as_uint(v.y);
    a[3] = __float_as_uint(v.w);
}
// B fragment from row-major [k][n] tile with stride SB (SB % 32 == 8):
// bank = 8*qc + qr (+const) -> conflict-free for both loads.
__device__ __forceinline__ void ldBk(uint32_t b[2], const float* Bs, int SB,
                                     int n0, int k0, int qr, int qc) {
    b[0] = __float_as_uint(Bs[(k0 + qc) * SB + n0 + qr]);
    b[1] = __float_as_uint(Bs[(k0 + qc + 4) * SB + n0 + qr]);
}
__device__ __forceinline__ float quad_sum(float v) {
    v += __shfl_xor_sync(0xffffffffu, v, 1);
    v += __shfl_xor_sync(0xffffffffu, v, 2);
    return v;
}
// cp.async helpers (baseline PTX, sm_80+)
__device__ __forceinline__ void cpa16(uint32_t saddr, const float* g) {
    asm volatile("cp.async.ca.shared.global [%0], [%1], 16;" :: "r"(saddr), "l"(g));
}
#define CPA_COMMIT() asm volatile("cp.async.commit_group;" ::: "memory")
#define CPA_WAIT0()  asm volatile("cp.async.wait_group 0;" ::: "memory")
__device__ __forceinline__ uint32_t smem_u32(const void* p) {
    return (uint32_t)__cvta_generic_to_shared(p);
}

// ---------------------------------------------------------------------------
// K0: pre-round weights to tf32 (rna) into g_wr.  225280 elems, 880x256.
// ---------------------------------------------------------------------------
__global__ __launch_bounds__(256) void k0_round(
    const float* __restrict__ W1, const float* __restrict__ W2,
    const float* __restrict__ Ws, const float* __restrict__ Wv)
{
    int i = blockIdx.x * 256 + threadIdx.x;
    float v;
    if (i < 4096)        v = W1[i];
    else if (i < 61440)  v = W2[i - 4096];
    else if (i < 159744) v = Ws[i - 61440];
    else                 v = Wv[i - 159744];
    g_wr[i] = tf32r(v);
}

// ---------------------------------------------------------------------------
// F1: fused rad-MLP. 128 edges/block, 8 warps (wm 0..3 x wn 0..1).
//   MMA1: hraw = es@W1 (M128,N64,K64); epi: h = silu(LN(hraw+b1)) -> packed A
//   7 passes: g_w[:, p*128..+128] = h@W2 + roff.  B via cp.async, pipelined.
// ---------------------------------------------------------------------------
#define F1_SMEM ((8192 + 8704 + 512) * 4)
__global__ __launch_bounds__(256, 2) void f1_kw(
    const float* __restrict__ es, const float* __restrict__ b1,
    const float* __restrict__ lg, const float* __restrict__ lb,
    const float* __restrict__ roff, int E)
{
    extern __shared__ float sm[];
    float4* As4 = (float4*)sm;              // 2048 quads (128 x 64)
    float*  Bs  = sm + 8192;                // [k][n] tiles: W1 SB=72, W2 SB=136
    float* redS = sm + 8192 + 8704;         // 256
    float* redQ = redS + 256;               // 256
    const uint32_t Bu = smem_u32(Bs);
    const int tid = threadIdx.x, wid = tid >> 5, lane = tid & 31;
    const int qr = lane >> 2, qc = lane & 3;
    const int e0 = blockIdx.x * 128;
    const int wm = wid & 3, wn = wid >> 2;

    // async-copy W1 tile ([k][n], SB=72) while building packed es tile
    for (int s = tid; s < 1024; s += 256) {
        int k = s >> 4, n4 = s & 15;
        cpa16(Bu + (uint32_t)(k * 72 + n4 * 4) * 4, g_wr + W1R_OFF + k * 64 + n4 * 4);
    }
    CPA_COMMIT();
    for (int qd = tid; qd < 2048; qd += 256) {
        int mt = qd >> 8, kg = (qd >> 5) & 7, ln = qd & 31;
        int ea = e0 + mt * 16 + (ln >> 2), ka = kg * 8 + (ln & 3);
        int eb = ea + 8;
        float v00 = (ea < E) ? es[(size_t)ea * 64 + ka] : 0.f;
        float v01 = (ea < E) ? es[(size_t)ea * 64 + ka + 4] : 0.f;
        float v10 = (eb < E) ? es[(size_t)eb * 64 + ka] : 0.f;
        float v11 = (eb < E) ? es[(size_t)eb * 64 + ka + 4] : 0.f;
        As4[qd] = make_float4(tf32r(v00), tf32r(v01), tf32r(v10), tf32r(v11));
    }
    CPA_WAIT0();
    __syncthreads();

    {   // ---- MMA1: warp tile 32 rows x 32 cols ----
        const int n0 = wn * 32;
        float acc[2][4][4];
#pragma unroll
        for (int mt = 0; mt < 2; mt++)
#pragma unroll
            for (int nt = 0; nt < 4; nt++)
#pragma unroll
                for (int f = 0; f < 4; f++) acc[mt][nt][f] = 0.f;
#pragma unroll
        for (int ks = 0; ks < 8; ks++) {
            uint32_t a[2][4];
            ldApk(a[0], As4, wm * 2, ks, lane);
            ldApk(a[1], As4, wm * 2 + 1, ks, lane);
#pragma unroll
            for (int nt = 0; nt < 4; nt++) {
                uint32_t b[2];
                ldBk(b, Bs, 72, n0 + nt * 8, ks * 8, qr, qc);
                mma8(acc[0][nt], a[0], b);
                mma8(acc[1][nt], a[1], b);
            }
        }
        __syncthreads();    // all warps done reading W1 tile
        // kick off W2 pass-0 copy; it flies during the LN/SiLU epilogue
        for (int s = tid; s < 2048; s += 256) {
            int k = s >> 5, n4 = s & 31;
            cpa16(Bu + (uint32_t)(k * 136 + n4 * 4) * 4, g_wr + W2R_OFF + k * 896 + n4 * 4);
        }
        CPA_COMMIT();

        // bias + stats + LN + silu -> write h into packed A tile
        float cb[8], cg[8], cB[8];
#pragma unroll
        for (int nt = 0; nt < 4; nt++)
#pragma unroll
            for (int c = 0; c < 2; c++) {
                int col = n0 + nt * 8 + qc * 2 + c;
                cb[nt * 2 + c] = b1[col]; cg[nt * 2 + c] = lg[col]; cB[nt * 2 + c] = lb[col];
            }
#pragma unroll
        for (int mt = 0; mt < 2; mt++)
#pragma unroll
            for (int h = 0; h < 2; h++) {
                float s = 0.f, q = 0.f;
#pragma unroll
                for (int nt = 0; nt < 4; nt++)
#pragma unroll
                    for (int c = 0; c < 2; c++) {
                        float v = acc[mt][nt][h * 2 + c] + cb[nt * 2 + c];
                        acc[mt][nt][h * 2 + c] = v;
                        s += v; q += v * v;
                    }
                s = quad_sum(s); q = quad_sum(q);
                if (qc == 0) {
                    int r = wm * 32 + mt * 16 + qr + h * 8;
                    redS[r * 2 + wn] = s; redQ[r * 2 + wn] = q;
                }
            }
        __syncthreads();
#pragma unroll
        for (int mt = 0; mt < 2; mt++)
#pragma unroll
            for (int h = 0; h < 2; h++) {
                int r = wm * 32 + mt * 16 + qr + h * 8;
                float s = redS[r * 2] + redS[r * 2 + 1];
                float q = redQ[r * 2] + redQ[r * 2 + 1];
                float mu = s * (1.f / 64.f);
                float rstd = rsqrtf(fmaxf(q * (1.f / 64.f) - mu * mu, 0.f) + EPS);
                int mtp = wm * 2 + mt;
#pragma unroll
                for (int nt = 0; nt < 4; nt++)
#pragma unroll
                    for (int c = 0; c < 2; c++) {
                        float v = (acc[mt][nt][h * 2 + c] - mu) * rstd * cg[nt * 2 + c] + cB[nt * 2 + c];
                        v = v / (1.f + expf(-v));
                        int col = n0 + nt * 8 + qc * 2 + c;
                        int word = ((mtp * 8 + (col >> 3)) * 32 + qr * 4 + (col & 3)) * 4
                                   + h * 2 + ((col >> 2) & 1);
                        sm[word] = tf32r(v);
                    }
            }
    }

    // ---- MMA2: 7 passes of N=128; warp tile 32 rows x 64 cols ----
    for (int p = 0; p < 7; p++) {
        CPA_WAIT0();
        __syncthreads();      // B(p) ready; h writes (p=0) / g_w stores done
        float acc[2][8][4];
#pragma unroll
        for (int mt = 0; mt < 2; mt++)
#pragma unroll
            for (int nt = 0; nt < 8; nt++)
#pragma unroll
                for (int f = 0; f < 4; f++) acc[mt][nt][f] = 0.f;
#pragma unroll
        for (int ks = 0; ks < 8; ks++) {
            uint32_t a[2][4];
            ldApk(a[0], As4, wm * 2, ks, lane);
            ldApk(a[1], As4, wm * 2 + 1, ks, lane);
#pragma unroll
            for (int nt = 0; nt < 8; nt++) {
                uint32_t b[2];
                ldBk(b, Bs, 136, wn * 64 + nt * 8, ks * 8, qr, qc);
                mma8(acc[0][nt], a[0], b);
                mma8(acc[1][nt], a[1], b);
            }
        }
        __syncthreads();      // all warps done reading B(p)
        if (p < 6) {          // next W2 chunk copy overlaps the g_w stores
            for (int s = tid; s < 2048; s += 256) {
                int k = s >> 5, n4 = s & 31;
                cpa16(Bu + (uint32_t)(k * 136 + n4 * 4) * 4,
                      g_wr + W2R_OFF + k * 896 + (p + 1) * 128 + n4 * 4);
            }
            CPA_COMMIT();
        }
#pragma unroll
        for (int mt = 0; mt < 2; mt++)
#pragma unroll
            for (int h = 0; h < 2; h++) {
                int r = wm * 32 + mt * 16 + qr + h * 8, ge = e0 + r;
                if (ge < E) {
#pragma unroll
                    for (int nt = 0; nt < 8; nt++) {
                        int colg = p * 128 + wn * 64 + nt * 8 + qc * 2;
                        float2 v;
                        v.x = acc[mt][nt][h * 2] + roff[colg];
                        v.y = acc[mt][nt][h * 2 + 1] + roff[colg + 1];
                        *(float2*)&g_w[(size_t)ge * 896 + colg] = v;
                    }
                }
            }
    }
}

// ---------------------------------------------------------------------------
// F2: scalar path. 64 edges/block (wm 0..1 x wn 0..3). A(64x384) per 64-K chunk.
// B (Ws) via cp.async [k][n] SB=264, copy overlapped with A-build.
// ---------------------------------------------------------------------------
__device__ __forceinline__ float f2_val(
    const float* __restrict__ node, const float* __restrict__ ysm,
    int e0, int E, int q, int e, int kk)
{
    int ge = e0 + e;
    if (ge >= E) return 0.f;
    if (q < 4) {
        int u = q * 64 + kk;
        return node[(size_t)ge * 640 + u] * ysm[e * 4] * g_w[(size_t)ge * 896 + u];
    } else {
        int j = (q - 4) * 64 + kk;
        const float* xp = node + (size_t)ge * 640 + 256 + 3 * j;
        float d = xp[0] * ysm[e * 4 + 1] + xp[1] * ysm[e * 4 + 2] + xp[2] * ysm[e * 4 + 3];
        return S3 * d * g_w[(size_t)ge * 896 + 640 + j];
    }
}

#define F2_SMEM ((4096 + 16896 + 256 + 512) * 4)
__global__ __launch_bounds__(256, 2) void f2_s(
    const float* __restrict__ node, const float* __restrict__ eattr,
    const float* __restrict__ bs, const float* __restrict__ gs,
    const float* __restrict__ gb, float* __restrict__ out, int E)
{
    extern __shared__ float sm[];
    float4* As4 = (float4*)sm;              // 1024 quads (64 x 64)
    float*  Bs  = sm + 4096;                // [k][n] SB=264, 64 rows
    float* ysm  = sm + 4096 + 16896;        // 256
    float* redS = ysm + 256;                // 256
    float* redQ = redS + 256;               // 256
    const uint32_t Bu = smem_u32(Bs);
    const int tid = threadIdx.x, wid = tid >> 5, lane = tid & 31;
    const int qr = lane >> 2, qc = lane & 3;
    const int e0 = blockIdx.x * 64;
    const int wm = wid & 1, wn = wid >> 1;

    {
        int ge = e0 + (tid >> 2);
        ysm[tid] = (ge < E) ? eattr[(size_t)ge * 4 + (tid & 3)] : 0.f;
    }
    // kick off B(0)
    for (int s = tid; s < 4096; s += 256) {
        int k = s >> 6, n4 = s & 63;
        cpa16(Bu + (uint32_t)(k * 264 + n4 * 4) * 4, g_wr + WSR_OFF + k * 256 + n4 * 4);
    }
    CPA_COMMIT();
    __syncthreads();        // ysm visible

    float acc[2][8][4];
#pragma unroll
    for (int mt = 0; mt < 2; mt++)
#pragma unroll
        for (int nt = 0; nt < 8; nt++)
#pragma unroll
            for (int f = 0; f < 4; f++) acc[mt][nt][f] = 0.f;

    for (int q = 0; q < 6; q++) {
        // build A(q) while B(q) copy is in flight
        for (int qd = tid; qd < 1024; qd += 256) {
            int mt = qd >> 8, kg = (qd >> 5) & 7, ln = qd & 31;
            int ea = mt * 16 + (ln >> 2), ka = kg * 8 + (ln & 3);
            float v00 = f2_val(node, ysm, e0, E, q, ea, ka);
            float v01 = f2_val(node, ysm, e0, E, q, ea, ka + 4);
            float v10 = f2_val(node, ysm, e0, E, q, ea + 8, ka);
            float v11 = f2_val(node, ysm, e0, E, q, ea + 8, ka + 4);
            As4[qd] = make_float4(tf32r(v00), tf32r(v01), tf32r(v10), tf32r(v11));
        }
        CPA_WAIT0();
        __syncthreads();
#pragma unroll
        for (int ks = 0; ks < 8; ks++) {
            uint32_t a[2][4];
            ldApk(a[0], As4, wm * 2, ks, lane);
            ldApk(a[1], As4, wm * 2 + 1, ks, lane);
#pragma unroll
            for (int nt = 0; nt < 8; nt++) {
                uint32_t b[2];
                ldBk(b, Bs, 264, wn * 64 + nt * 8, ks * 8, qr, qc);
                mma8(acc[0][nt], a[0], b);
                mma8(acc[1][nt], a[1], b);
            }
        }
        __syncthreads();
        if (q < 5) {
            for (int s = tid; s < 4096; s += 256) {
                int k = s >> 6, n4 = s & 63;
                cpa16(Bu + (uint32_t)(k * 264 + n4 * 4) * 4,
                      g_wr + WSR_OFF + ((q + 1) * 64 + k) * 256 + n4 * 4);
            }
            CPA_COMMIT();
        }
    }

    // ---- epilogue: +bias, LN over 256 cols (cross 4 N-warps), write ----
    float cb[16], cg[16], cB[16];
#pragma unroll
    for (int nt = 0; nt < 8; nt++)
#pragma unroll
        for (int c = 0; c < 2; c++) {
            int col = wn * 64 + nt * 8 + qc * 2 + c;
            cb[nt * 2 + c] = bs[col]; cg[nt * 2 + c] = gs[col]; cB[nt * 2 + c] = gb[col];
        }
#pragma unroll
    for (int mt = 0; mt < 2; mt++)
#pragma unroll
        for (int h = 0; h < 2; h++) {
            float s = 0.f, q = 0.f;
#pragma unroll
            for (int nt = 0; nt < 8; nt++)
#pragma unroll
                for (int c = 0; c < 2; c++) {
                    float v = acc[mt][nt][h * 2 + c] + cb[nt * 2 + c];
                    acc[mt][nt][h * 2 + c] = v;
                    s += v; q += v * v;
                }
            s = quad_sum(s); q = quad_sum(q);
            if (qc == 0) {
                int r = wm * 32 + mt * 16 + qr + h * 8;
                redS[r * 4 + wn] = s; redQ[r * 4 + wn] = q;
            }
        }
    __syncthreads();
#pragma unroll
    for (int mt = 0; mt < 2; mt++)
#pragma unroll
        for (int h = 0; h < 2; h++) {
            int r = wm * 32 + mt * 16 + qr + h * 8, ge = e0 + r;
            float s = redS[r * 4] + redS[r * 4 + 1] + redS[r * 4 + 2] + redS[r * 4 + 3];
            float q = redQ[r * 4] + redQ[r * 4 + 1] + redQ[r * 4 + 2] + redQ[r * 4 + 3];
            float mu = s * (1.f / 256.f);
            float rstd = rsqrtf(fmaxf(q * (1.f / 256.f) - mu * mu, 0.f) + EPS);
            if (ge < E) {
#pragma unroll
                for (int nt = 0; nt < 8; nt++) {
                    int col = wn * 64 + nt * 8 + qc * 2;
                    float2 v;
                    v.x = (acc[mt][nt][h * 2] - mu) * rstd * cg[nt * 2] + cB[nt * 2];
                    v.y = (acc[mt][nt][h * 2 + 1] - mu) * rstd * cg[nt * 2 + 1] + cB[nt * 2 + 1];
                    *(float2*)&out[(size_t)ge * 640 + col] = v;
                }
            }
        }
}

// ---------------------------------------------------------------------------
// F3: vector path, 4-plane formulation.  64 edges/block, 512 threads
// (wm 0..1 x wn 0..7, warp tile 32 x 16).  B (Wv) via cp.async SB=136.
// ---------------------------------------------------------------------------
#define F3_SMEM ((12288 + 8704 + 256 + 512) * 4)
__global__ __launch_bounds__(512, 1) void f3_v(
    const float* __restrict__ node, const float* __restrict__ eattr,
    const float* __restrict__ gv, float* __restrict__ out, int E)
{
    extern __shared__ float sm[];
    float4* A04 = (float4*)sm;                  // 1024 quads each
    float4* A14 = A04 + 1024;
    float4* A24 = A14 + 1024;
    float*  Bs  = sm + 12288;                   // [k][n] SB=136
    float* ysm  = sm + 12288 + 8704;            // 256
    float* redQ = ysm + 256;                    // 512
    const uint32_t Bu = smem_u32(Bs);
    const int tid = threadIdx.x, wid = tid >> 5, lane = tid & 31;
    const int qr = lane >> 2, qc = lane & 3;
    const int e0 = blockIdx.x * 64;
    const int wm = wid & 1, wn = wid >> 1;      // wn 0..7
    const int n0 = wn * 16;

    if (tid < 256) {
        int ge = e0 + (tid >> 2);
        ysm[tid] = (ge < E) ? eattr[(size_t)ge * 4 + (tid & 3)] : 0.f;
    }
    for (int s = tid; s < 2048; s += 512) {
        int k = s >> 5, n4 = s & 31;
        cpa16(Bu + (uint32_t)(k * 136 + n4 * 4) * 4, g_wr + WVR_OFF + k * 128 + n4 * 4);
    }
    CPA_COMMIT();
    __syncthreads();

    float accR[2][2][4];
    float accM[3][2][2][4];
#pragma unroll
    for (int mt = 0; mt < 2; mt++)
#pragma unroll
        for (int nt = 0; nt < 2; nt++)
#pragma unroll
            for (int f = 0; f < 4; f++) {
                accR[mt][nt][f] = 0.f;
#pragma unroll
                for (int m = 0; m < 3; m++) accM[m][mt][nt][f] = 0.f;
            }

    for (int q = 0; q < 8; q++) {
        if (q < 4) {
            for (int qd = tid; qd < 1024; qd += 512) {
                int mt = qd >> 8, kg = (qd >> 5) & 7, ln = qd & 31;
                int ea = mt * 16 + (ln >> 2), ka = kg * 8 + (ln & 3);
                float v[4];
#pragma unroll
                for (int t = 0; t < 4; t++) {
                    int e = ea + (t >> 1) * 8, kk = ka + (t & 1) * 4;
                    int ge = e0 + e;
                    int u = q * 64 + kk;
                    v[t] = (ge < E)
                         ? node[(size_t)ge * 640 + u] * g_w[(size_t)ge * 896 + 256 + u]
                         : 0.f;
                }
                A04[qd] = make_float4(tf32r(v[0]), tf32r(v[1]), tf32r(v[2]), tf32r(v[3]));
            }
        } else {
            for (int qd = tid; qd < 1024; qd += 512) {
                int mt = qd >> 8, kg = (qd >> 5) & 7, ln = qd & 31;
                int ea = mt * 16 + (ln >> 2), ka = kg * 8 + (ln & 3);
                float a0[4], a1[4], a2[4];
#pragma unroll
                for (int t = 0; t < 4; t++) {
                    int e = ea + (t >> 1) * 8, kk = ka + (t & 1) * 4;
                    int ge = e0 + e;
                    a0[t] = a1[t] = a2[t] = 0.f;
                    if (ge < E) {
                        if (q < 6) {
                            int j = (q - 4) * 64 + kk;
                            const float* xp = node + (size_t)ge * 640 + 256 + 3 * j;
                            float f = ysm[e * 4] * g_w[(size_t)ge * 896 + 512 + j];
                            a0[t] = xp[0] * f; a1[t] = xp[1] * f; a2[t] = xp[2] * f;
                        } else {
                            int j = (q - 6) * 64 + kk;
                            const float* xp = node + (size_t)ge * 640 + 256 + 3 * j;
                            float x0v = xp[0], x1v = xp[1], x2v = xp[2];
                            float z0 = ysm[e * 4 + 1], z1 = ysm[e * 4 + 2], z2 = ysm[e * 4 + 3];
                            float f = S2 * g_w[(size_t)ge * 896 + 768 + j];
                            a0[t] = (x1v * z2 - x2v * z1) * f;
                            a1[t] = (x2v * z0 - x0v * z2) * f;
                            a2[t] = (x0v * z1 - x1v * z0) * f;
                        }
                    }
                }
                A04[qd] = make_float4(tf32r(a0[0]), tf32r(a0[1]), tf32r(a0[2]), tf32r(a0[3]));
                A14[qd] = make_float4(tf32r(a1[0]), tf32r(a1[1]), tf32r(a1[2]), tf32r(a1[3]));
                A24[qd] = make_float4(tf32r(a2[0]), tf32r(a2[1]), tf32r(a2[2]), tf32r(a2[3]));
            }
        }
        CPA_WAIT0();
        __syncthreads();

        if (q < 4) {
#pragma unroll
            for (int ks = 0; ks < 8; ks++) {
                uint32_t a[2][4];
                ldApk(a[0], A04, wm * 2, ks, lane);
                ldApk(a[1], A04, wm * 2 + 1, ks, lane);
#pragma unroll
                for (int nt = 0; nt < 2; nt++) {
                    uint32_t b[2];
                    ldBk(b, Bs, 136, n0 + nt * 8, ks * 8, qr, qc);
                    mma8(accR[0][nt], a[0], b);
                    mma8(accR[1][nt], a[1], b);
                }
            }
        } else {
#pragma unroll
            for (int ks = 0; ks < 8; ks++) {
                uint32_t b[2][2];
#pragma unroll
                for (int nt = 0; nt < 2; nt++) ldBk(b[nt], Bs, 136, n0 + nt * 8, ks * 8, qr, qc);
                const float4* Ap[3] = {A04, A14, A24};
#pragma unroll
                for (int m = 0; m < 3; m++) {
                    uint32_t a[2][4];
                    ldApk(a[0], Ap[m], wm * 2, ks, lane);
                    ldApk(a[1], Ap[m], wm * 2 + 1, ks, lane);
#pragma unroll
                    for (int nt = 0; nt < 2; nt++) {
                        mma8(accM[m][0][nt], a[0], b[nt]);
                        mma8(accM[m][1][nt], a[1], b[nt]);
                    }
                }
            }
        }
        __syncthreads();
        if (q < 7) {
            for (int s = tid; s < 2048; s += 512) {
                int k = s >> 5, n4 = s & 31;
                cpa16(Bu + (uint32_t)(k * 136 + n4 * 4) * 4,
                      g_wr + WVR_OFF + ((q + 1) * 64 + k) * 128 + n4 * 4);
            }
            CPA_COMMIT();
        }
    }

    // ---- epilogue: fold R plane, sumsq, norm, write ----
#pragma unroll
    for (int mt = 0; mt < 2; mt++)
#pragma unroll
        for (int h = 0; h < 2; h++) {
            int e = wm * 32 + mt * 16 + qr + h * 8;
            float z0 = ysm[e * 4 + 1], z1 = ysm[e * 4 + 2], z2 = ysm[e * 4 + 3];
            float s = 0.f;
#pragma unroll
            for (int nt = 0; nt < 2; nt++)
#pragma unroll
                for (int c = 0; c < 2; c++) {
                    float R = accR[mt][nt][h * 2 + c];
                    float v0 = z0 * R + accM[0][mt][nt][h * 2 + c];
                    float v1 = z1 * R + accM[1][mt][nt][h * 2 + c];
                    float v2 = z2 * R + accM[2][mt][nt][h * 2 + c];
                    accM[0][mt][nt][h * 2 + c] = v0;
                    accM[1][mt][nt][h * 2 + c] = v1;
                    accM[2][mt][nt][h * 2 + c] = v2;
                    s += v0 * v0 + v1 * v1 + v2 * v2;
                }
            s = quad_sum(s);
            if (qc == 0) redQ[e * 8 + wn] = s;
        }
    __syncthreads();
    float cg[4];
#pragma unroll
    for (int nt = 0; nt < 2; nt++)
#pragma unroll
        for (int c = 0; c < 2; c++) cg[nt * 2 + c] = gv[n0 + nt * 8 + qc * 2 + c];
#pragma unroll
    for (int mt = 0; mt < 2; mt++)
#pragma unroll
        for (int h = 0; h < 2; h++) {
            int e = wm * 32 + mt * 16 + qr + h * 8, ge = e0 + e;
            float qt = 0.f;
#pragma unroll
            for (int w8 = 0; w8 < 8; w8++) qt += redQ[e * 8 + w8];
            float rstd = rsqrtf(qt * (1.f / 384.f) + EPS);
            if (ge < E) {
                float* ob = out + (size_t)ge * 640 + 256;
#pragma unroll
                for (int nt = 0; nt < 2; nt++)
#pragma unroll
                    for (int c = 0; c < 2; c++) {
                        int col = n0 + nt * 8 + qc * 2 + c;
                        float g = cg[nt * 2 + c] * rstd;
                        ob[3 * col + 0] = accM[0][mt][nt][h * 2 + c] * g;
                        ob[3 * col + 1] = accM[1][mt][nt][h * 2 + c] * g;
                        ob[3 * col + 2] = accM[2][mt][nt][h * 2 + c] * g;
                    }
            }
        }
}

// ---------------------------------------------------------------------------
extern "C" void kernel_launch(void* const* d_in, const int* in_sizes, int n_in,
                              void* d_out, int out_size)
{
    const float* node  = (const float*)d_in[0];   // (E, 640)
    const float* eattr = (const float*)d_in[1];   // (E, 4)
    const float* escal = (const float*)d_in[2];   // (E, 64)
    const float* rW1   = (const float*)d_in[3];   // (64, 64)
    const float* rb1   = (const float*)d_in[4];   // (64,)
    const float* rlg   = (const float*)d_in[5];   // (64,)
    const float* rlb   = (const float*)d_in[6];   // (64,)
    const float* rW2   = (const float*)d_in[7];   // (64, 896)
    const float* roff  = (const float*)d_in[8];   // (896,)
    const float* Ws    = (const float*)d_in[9];   // (384, 256)
    const float* bs    = (const float*)d_in[10];  // (256,)
    const float* Wv    = (const float*)d_in[11];  // (512, 128)
    const float* gs    = (const float*)d_in[12];  // (256,)
    const float* gb    = (const float*)d_in[13];  // (256,)
    const float* gv    = (const float*)d_in[14];  // (128,)
    float* out = (float*)d_out;

    const int E = in_sizes[1] / 4;
    const int nb128 = (E + 127) / 128;
    const int nb64  = (E + 63) / 64;

    cudaFuncSetAttribute(f1_kw, cudaFuncAttributeMaxDynamicSharedMemorySize, F1_SMEM);
    cudaFuncSetAttribute(f2_s,  cudaFuncAttributeMaxDynamicSharedMemorySize, F2_SMEM);
    cudaFuncSetAttribute(f3_v,  cudaFuncAttributeMaxDynamicSharedMemorySize, F3_SMEM);

    k0_round<<<880, 256>>>(rW1, rW2, Ws, Wv);
    f1_kw<<<nb128, 256, F1_SMEM>>>(escal, rb1, rlg, rlb, roff, E);
    f2_s<<<nb64, 256, F2_SMEM>>>(node, eattr, bs, gs, gb, out, E);
    f3_v<<<nb64, 512, F3_SMEM>>>(node, eattr, gv, out, E);
}

// round 11
// speedup vs baseline: 2.3788x; 1.0176x over previous
#include <cuda_runtime.h>
#include <math.h>
#include <stdint.h>

#define S3 0.5773502691896258f
#define S2 0.7071067811865476f
#define EPS 1e-5f

// pre-rounded (tf32 rna) weights: W1[4096] | W2[57344] | Ws[98304] | Wv[65536]
__device__ float g_wr[225280];
#define W1R_OFF 0
#define W2R_OFF 4096
#define WSR_OFF 61440
#define WVR_OFF 159744

__device__ __forceinline__ float tf32r(float x) {
    uint32_t u;
    asm("cvt.rna.tf32.f32 %0, %1;" : "=r"(u) : "f"(x));
    return __uint_as_float(u);
}
// mma.sync m16n8k8 tf32: D += A(16x8) * B(8x8)^T, fp32 accum (baseline PTX, sm_80+)
__device__ __forceinline__ void mma8(float d[4], const uint32_t a[4], const uint32_t b[2]) {
    asm volatile(
        "mma.sync.aligned.m16n8k8.row.col.f32.tf32.tf32.f32 "
        "{%0,%1,%2,%3}, {%4,%5,%6,%7}, {%8,%9}, {%0,%1,%2,%3};"
        : "+f"(d[0]), "+f"(d[1]), "+f"(d[2]), "+f"(d[3])
        : "r"(a[0]), "r"(a[1]), "r"(a[2]), "r"(a[3]), "r"(b[0]), "r"(b[1]));
}
// Packed A tile: quad (mt,ks,lane) = [(r,k),(r,k+4),(r+8,k),(r+8,k+4)],
// r = mt*16 + lane/4, k = ks*8 + lane%4.  One LDS.128 per fragment.
__device__ __forceinline__ void ldApk(uint32_t a[4], const float4* Ap, int mt, int ks, int lane) {
    float4 v = Ap[(mt * 8 + ks) * 32 + lane];
    a[0] = __float_as_uint(v.x);
    a[1] = __float_as_uint(v.z);
    a[2] = __float_as_uint(v.y);
    a[3] = __float_as_uint(v.w);
}
// B fragment from row-major [k][n] tile, stride SB (SB % 32 == 8) -> conflict-free
__device__ __forceinline__ void ldBk(uint32_t b[2], const float* Bs, int SB,
                                     int n0, int k0, int qr, int qc) {
    b[0] = __float_as_uint(Bs[(k0 + qc) * SB + n0 + qr]);
    b[1] = __float_as_uint(Bs[(k0 + qc + 4) * SB + n0 + qr]);
}
__device__ __forceinline__ float quad_sum(float v) {
    v += __shfl_xor_sync(0xffffffffu, v, 1);
    v += __shfl_xor_sync(0xffffffffu, v, 2);
    return v;
}
__device__ __forceinline__ void cpa16(uint32_t saddr, const float* g) {
    asm volatile("cp.async.ca.shared.global [%0], [%1], 16;" :: "r"(saddr), "l"(g));
}
#define CPA_COMMIT() asm volatile("cp.async.commit_group;" ::: "memory")
#define CPA_WAIT0()  asm volatile("cp.async.wait_group 0;" ::: "memory")
#define CPA_WAIT1()  asm volatile("cp.async.wait_group 1;" ::: "memory")
__device__ __forceinline__ uint32_t smem_u32(const void* p) {
    return (uint32_t)__cvta_generic_to_shared(p);
}

// ---------------------------------------------------------------------------
// K0: pre-round weights to tf32 (rna) into g_wr.  225280 elems = 880x256.
// ---------------------------------------------------------------------------
__global__ __launch_bounds__(256) void k0_round(
    const float* __restrict__ W1, const float* __restrict__ W2,
    const float* __restrict__ Ws, const float* __restrict__ Wv)
{
    int i = blockIdx.x * 256 + threadIdx.x;
    float v;
    if (i < 4096)        v = W1[i];
    else if (i < 61440)  v = W2[i - 4096];
    else if (i < 159744) v = Ws[i - 61440];
    else                 v = Wv[i - 159744];
    g_wr[i] = tf32r(v);
}

// ===========================================================================
// Shared per-block stage (both kernels): compute packed h tile for 64 edges.
//   Ah (sm offset 0, packed) starts as es, ends as h = silu(LN(es@W1 + b1)).
//   W1 tile lives in the Bm buffer (SB=72) during this stage.
// Layout (512 thr): wm = wid&1 (M 32-half), wn = wid>>1 (0..7, 8 N-cols each)
// ===========================================================================
#define H_STAGE(sm, Ah4, Bm, redS, redQ)                                          \
{                                                                                 \
    float hacc[2][4];                                                             \
    _Pragma("unroll") for (int mt = 0; mt < 2; mt++)                              \
        _Pragma("unroll") for (int f = 0; f < 4; f++) hacc[mt][f] = 0.f;          \
    _Pragma("unroll") for (int ks = 0; ks < 8; ks++) {                            \
        uint32_t a0[4], a1[4], b[2];                                              \
        ldApk(a0, Ah4, wm * 2, ks, lane);                                         \
        ldApk(a1, Ah4, wm * 2 + 1, ks, lane);                                     \
        ldBk(b, Bm, 72, wn * 8, ks * 8, qr, qc);                                  \
        mma8(hacc[0], a0, b);                                                     \
        mma8(hacc[1], a1, b);                                                     \
    }                                                                             \
    __syncthreads();  /* done reading W1 (Bm) and es (Ah) */                      \
    /* commit Bmain(0) into Bm (overwrites W1) */                                 \
    COMMIT_BMAIN(0);                                                              \
    float cb[2], cgl[2], cBl[2];                                                  \
    _Pragma("unroll") for (int c = 0; c < 2; c++) {                               \
        int col = wn * 8 + qc * 2 + c;                                            \
        cb[c] = b1[col]; cgl[c] = lg[col]; cBl[c] = lb[col];                      \
    }                                                                             \
    _Pragma("unroll") for (int mt = 0; mt < 2; mt++)                              \
        _Pragma("unroll") for (int h = 0; h < 2; h++) {                           \
            float s = 0.f, q = 0.f;                                               \
            _Pragma("unroll") for (int c = 0; c < 2; c++) {                       \
                float v = hacc[mt][h * 2 + c] + cb[c];                            \
                hacc[mt][h * 2 + c] = v;                                          \
                s += v; q += v * v;                                               \
            }                                                                     \
            s = quad_sum(s); q = quad_sum(q);                                     \
            if (qc == 0) {                                                        \
                int r = wm * 32 + mt * 16 + qr + h * 8;                           \
                redS[r * 8 + wn] = s; redQ[r * 8 + wn] = q;                       \
            }                                                                     \
        }                                                                         \
    __syncthreads();                                                              \
    _Pragma("unroll") for (int mt = 0; mt < 2; mt++)                              \
        _Pragma("unroll") for (int h = 0; h < 2; h++) {                           \
            int r = wm * 32 + mt * 16 + qr + h * 8;                               \
            float s = 0.f, q = 0.f;                                               \
            _Pragma("unroll") for (int w8 = 0; w8 < 8; w8++) {                    \
                s += redS[r * 8 + w8]; q += redQ[r * 8 + w8];                     \
            }                                                                     \
            float mu = s * (1.f / 64.f);                                          \
            float rstd = rsqrtf(fmaxf(q * (1.f / 64.f) - mu * mu, 0.f) + EPS);    \
            int mtp = wm * 2 + mt;                                                \
            _Pragma("unroll") for (int c = 0; c < 2; c++) {                       \
                float v = (hacc[mt][h * 2 + c] - mu) * rstd * cgl[c] + cBl[c];    \
                v = v / (1.f + expf(-v));                                         \
                int col = wn * 8 + qc * 2 + c;                                    \
                int word = ((mtp * 8 + (col >> 3)) * 32 + qr * 4 + (col & 3)) * 4 \
                           + h * 2 + ((col >> 2) & 1);                            \
                sm[word] = tf32r(v);                                              \
            }                                                                     \
        }                                                                         \
    __syncthreads();                                                              \
}

// wMMA stage: w-slice (64 cols) = h @ W2cols(q) + roff -> wsm (stride 68)
#define W_STAGE(Ah4, W2t, wsm, base)                                              \
{                                                                                 \
    float wacc[2][4];                                                             \
    _Pragma("unroll") for (int mt = 0; mt < 2; mt++)                              \
        _Pragma("unroll") for (int f = 0; f < 4; f++) wacc[mt][f] = 0.f;          \
    _Pragma("unroll") for (int ks = 0; ks < 8; ks++) {                            \
        uint32_t a0[4], a1[4], b[2];                                              \
        ldApk(a0, Ah4, wm * 2, ks, lane);                                         \
        ldApk(a1, Ah4, wm * 2 + 1, ks, lane);                                     \
        ldBk(b, W2t, 72, wn * 8, ks * 8, qr, qc);                                 \
        mma8(wacc[0], a0, b);                                                     \
        mma8(wacc[1], a1, b);                                                     \
    }                                                                             \
    __syncthreads();  /* done reading W2t */                                      \
    COMMIT_W2_NEXT();                                                             \
    _Pragma("unroll") for (int mt = 0; mt < 2; mt++)                              \
        _Pragma("unroll") for (int h = 0; h < 2; h++) {                           \
            int r = wm * 32 + mt * 16 + qr + h * 8;                               \
            _Pragma("unroll") for (int c = 0; c < 2; c++) {                       \
                int u = wn * 8 + qc * 2 + c;                                      \
                wsm[r * 68 + u] = wacc[mt][h * 2 + c] + roff[base + u];           \
            }                                                                     \
        }                                                                         \
    __syncthreads();  /* wsm visible */                                           \
}

// ---------------------------------------------------------------------------
// F2: scalar path (fused). 64 edges/block, 512 threads, 1 CTA.
// smem(floats): Ah 0..4095 | As 4096..8191 | Bm 8192..25087 (SB=264)
//   | W2t 25088..29695 (SB=72) | wsm 29696..34047 (s68) | ysm 34048
//   | redS 34304 | redQ 34816 | total 35328
// ---------------------------------------------------------------------------
#define F2_SMEM (35328 * 4)
__global__ __launch_bounds__(512, 1) void f2_s(
    const float* __restrict__ node, const float* __restrict__ eattr,
    const float* __restrict__ es,
    const float* __restrict__ b1, const float* __restrict__ lg,
    const float* __restrict__ lb, const float* __restrict__ roff,
    const float* __restrict__ bs, const float* __restrict__ gs,
    const float* __restrict__ gb, float* __restrict__ out, int E)
{
    extern __shared__ float sm[];
    float4* Ah4 = (float4*)sm;
    float4* As4 = (float4*)(sm + 4096);
    float*  Bm  = sm + 8192;
    float*  W2t = sm + 25088;
    float*  wsm = sm + 29696;
    float*  ysm = sm + 34048;
    float* redS = sm + 34304;
    float* redQ = sm + 34816;
    const uint32_t BmU = smem_u32(Bm), W2U = smem_u32(W2t);
    const int tid = threadIdx.x, wid = tid >> 5, lane = tid & 31;
    const int qr = lane >> 2, qc = lane & 3;
    const int e0 = blockIdx.x * 64;
    const int wm = wid & 1, wn = wid >> 1;
    const int Q = 6;

#define COMMIT_BMAIN(qq) do {                                                     \
    for (int s = tid; s < 4096; s += 512) {                                       \
        int k = s >> 6, n4 = s & 63;                                              \
        cpa16(BmU + (uint32_t)(k * 264 + n4 * 4) * 4,                             \
              g_wr + WSR_OFF + ((qq) * 64 + k) * 256 + n4 * 4);                   \
    }                                                                             \
    CPA_COMMIT(); } while (0)
#define COMMIT_W2_NEXT() do {                                                     \
    if (q + 1 < Q) {                                                              \
        int nb = (q + 1 < 4) ? (q + 1) * 64 : 640 + (q + 1 - 4) * 64;             \
        for (int s = tid; s < 1024; s += 512) {                                   \
            int k = s >> 4, n4 = s & 15;                                          \
            cpa16(W2U + (uint32_t)(k * 72 + n4 * 4) * 4,                          \
                  g_wr + W2R_OFF + k * 896 + nb + n4 * 4);                        \
        }                                                                         \
        CPA_COMMIT();                                                             \
    } } while (0)

    // G1: W1 -> Bm
    for (int s = tid; s < 1024; s += 512) {
        int k = s >> 4, n4 = s & 15;
        cpa16(BmU + (uint32_t)(k * 72 + n4 * 4) * 4, g_wr + W1R_OFF + k * 64 + n4 * 4);
    }
    CPA_COMMIT();
    // G2: W2cols(0) -> W2t
    for (int s = tid; s < 1024; s += 512) {
        int k = s >> 4, n4 = s & 15;
        cpa16(W2U + (uint32_t)(k * 72 + n4 * 4) * 4, g_wr + W2R_OFF + k * 896 + n4 * 4);
    }
    CPA_COMMIT();
    if (tid < 256) {
        int ge = e0 + (tid >> 2);
        ysm[tid] = (ge < E) ? eattr[(size_t)ge * 4 + (tid & 3)] : 0.f;
    }
    for (int qd = tid; qd < 1024; qd += 512) {
        int mt = qd >> 8, kg = (qd >> 5) & 7, ln = qd & 31;
        int ea = e0 + mt * 16 + (ln >> 2), ka = kg * 8 + (ln & 3);
        int eb = ea + 8;
        float v00 = (ea < E) ? es[(size_t)ea * 64 + ka] : 0.f;
        float v01 = (ea < E) ? es[(size_t)ea * 64 + ka + 4] : 0.f;
        float v10 = (eb < E) ? es[(size_t)eb * 64 + ka] : 0.f;
        float v11 = (eb < E) ? es[(size_t)eb * 64 + ka + 4] : 0.f;
        Ah4[qd] = make_float4(tf32r(v00), tf32r(v01), tf32r(v10), tf32r(v11));
    }
    CPA_WAIT1();
    __syncthreads();

    H_STAGE(sm, Ah4, Bm, redS, redQ)

    float acc[2][4][4];
#pragma unroll
    for (int mt = 0; mt < 2; mt++)
#pragma unroll
        for (int nt = 0; nt < 4; nt++)
#pragma unroll
            for (int f = 0; f < 4; f++) acc[mt][nt][f] = 0.f;

    for (int q = 0; q < Q; q++) {
        CPA_WAIT1();          // W2t(q) ready (Bmain(q) may pend)
        __syncthreads();
        {
            int base = (q < 4) ? q * 64 : 640 + (q - 4) * 64;
            W_STAGE(Ah4, W2t, wsm, base)
        }
        // build As(q) from node + wsm
        for (int qd = tid; qd < 1024; qd += 512) {
            int mt = qd >> 8, kg = (qd >> 5) & 7, ln = qd & 31;
            int ea = mt * 16 + (ln >> 2), ka = kg * 8 + (ln & 3);
            float v[4];
#pragma unroll
            for (int t = 0; t < 4; t++) {
                int e = ea + (t >> 1) * 8, kk = ka + (t & 1) * 4;
                int ge = e0 + e;
                v[t] = 0.f;
                if (ge < E) {
                    if (q < 4) {
                        v[t] = node[(size_t)ge * 640 + q * 64 + kk] * ysm[e * 4]
                             * wsm[e * 68 + kk];
                    } else {
                        int j = (q - 4) * 64 + kk;
                        const float* xp = node + (size_t)ge * 640 + 256 + 3 * j;
                        float d = xp[0] * ysm[e * 4 + 1] + xp[1] * ysm[e * 4 + 2]
                                + xp[2] * ysm[e * 4 + 3];
                        v[t] = S3 * d * wsm[e * 68 + kk];
                    }
                }
            }
            As4[qd] = make_float4(tf32r(v[0]), tf32r(v[1]), tf32r(v[2]), tf32r(v[3]));
        }
        if (q + 1 < Q) CPA_WAIT1(); else CPA_WAIT0();   // Bmain(q) ready
        __syncthreads();
#pragma unroll
        for (int ks = 0; ks < 8; ks++) {
            uint32_t a0[4], a1[4];
            ldApk(a0, As4, wm * 2, ks, lane);
            ldApk(a1, As4, wm * 2 + 1, ks, lane);
#pragma unroll
            for (int nt = 0; nt < 4; nt++) {
                uint32_t b[2];
                ldBk(b, Bm, 264, wn * 32 + nt * 8, ks * 8, qr, qc);
                mma8(acc[0][nt], a0, b);
                mma8(acc[1][nt], a1, b);
            }
        }
        __syncthreads();
        if (q + 1 < Q) COMMIT_BMAIN(q + 1);
    }

    // epilogue: +bias, LN over 256 cols (cross 8 wn warps), write
    float cbv[8], cgv[8], cBv[8];
#pragma unroll
    for (int nt = 0; nt < 4; nt++)
#pragma unroll
        for (int c = 0; c < 2; c++) {
            int col = wn * 32 + nt * 8 + qc * 2 + c;
            cbv[nt * 2 + c] = bs[col]; cgv[nt * 2 + c] = gs[col]; cBv[nt * 2 + c] = gb[col];
        }
#pragma unroll
    for (int mt = 0; mt < 2; mt++)
#pragma unroll
        for (int h = 0; h < 2; h++) {
            float s = 0.f, q2 = 0.f;
#pragma unroll
            for (int nt = 0; nt < 4; nt++)
#pragma unroll
                for (int c = 0; c < 2; c++) {
                    float v = acc[mt][nt][h * 2 + c] + cbv[nt * 2 + c];
                    acc[mt][nt][h * 2 + c] = v;
                    s += v; q2 += v * v;
                }
            s = quad_sum(s); q2 = quad_sum(q2);
            if (qc == 0) {
                int r = wm * 32 + mt * 16 + qr + h * 8;
                redS[r * 8 + wn] = s; redQ[r * 8 + wn] = q2;
            }
        }
    __syncthreads();
#pragma unroll
    for (int mt = 0; mt < 2; mt++)
#pragma unroll
        for (int h = 0; h < 2; h++) {
            int r = wm * 32 + mt * 16 + qr + h * 8, ge = e0 + r;
            float s = 0.f, q2 = 0.f;
#pragma unroll
            for (int w8 = 0; w8 < 8; w8++) { s += redS[r * 8 + w8]; q2 += redQ[r * 8 + w8]; }
            float mu = s * (1.f / 256.f);
            float rstd = rsqrtf(fmaxf(q2 * (1.f / 256.f) - mu * mu, 0.f) + EPS);
            if (ge < E) {
#pragma unroll
                for (int nt = 0; nt < 4; nt++) {
                    int col = wn * 32 + nt * 8 + qc * 2;
                    float2 v;
                    v.x = (acc[mt][nt][h * 2] - mu) * rstd * cgv[nt * 2] + cBv[nt * 2];
                    v.y = (acc[mt][nt][h * 2 + 1] - mu) * rstd * cgv[nt * 2 + 1] + cBv[nt * 2 + 1];
                    *(float2*)&out[(size_t)ge * 640 + col] = v;
                }
            }
        }
#undef COMMIT_BMAIN
#undef COMMIT_W2_NEXT
}

// ---------------------------------------------------------------------------
// F3: vector path (fused), 4-plane formulation. 64 edges/block, 512 threads.
// smem(floats): Ah 0..4095 | A0 4096 | A1 8192 | A2 12288 | Bm 16384..25087
//   (SB=136) | W2t 25088 (SB=72) | wsm 29696 (s68) | ysm 34048 | redS 34304
//   | redQ 34816 | total 35328
// ---------------------------------------------------------------------------
#define F3_SMEM (35328 * 4)
__global__ __launch_bounds__(512, 1) void f3_v(
    const float* __restrict__ node, const float* __restrict__ eattr,
    const float* __restrict__ es,
    const float* __restrict__ b1, const float* __restrict__ lg,
    const float* __restrict__ lb, const float* __restrict__ roff,
    const float* __restrict__ gv, float* __restrict__ out, int E)
{
    extern __shared__ float sm[];
    float4* Ah4 = (float4*)sm;
    float4* A04 = (float4*)(sm + 4096);
    float4* A14 = (float4*)(sm + 8192);
    float4* A24 = (float4*)(sm + 12288);
    float*  Bm  = sm + 16384;
    float*  W2t = sm + 25088;
    float*  wsm = sm + 29696;
    float*  ysm = sm + 34048;
    float* redS = sm + 34304;
    float* redQ = sm + 34816;
    const uint32_t BmU = smem_u32(Bm), W2U = smem_u32(W2t);
    const int tid = threadIdx.x, wid = tid >> 5, lane = tid & 31;
    const int qr = lane >> 2, qc = lane & 3;
    const int e0 = blockIdx.x * 64;
    const int wm = wid & 1, wn = wid >> 1;
    const int n0 = wn * 16;
    const int Q = 8;

#define COMMIT_BMAIN(qq) do {                                                     \
    for (int s = tid; s < 2048; s += 512) {                                       \
        int k = s >> 5, n4 = s & 31;                                              \
        cpa16(BmU + (uint32_t)(k * 136 + n4 * 4) * 4,                             \
              g_wr + WVR_OFF + ((qq) * 64 + k) * 128 + n4 * 4);                   \
    }                                                                             \
    CPA_COMMIT(); } while (0)
#define COMMIT_W2_NEXT() do {                                                     \
    if (q + 1 < Q) {                                                              \
        int qq = q + 1;                                                           \
        int nb = (qq < 4) ? 256 + qq * 64 : (qq < 6 ? 512 + (qq - 4) * 64         \
                                                    : 768 + (qq - 6) * 64);       \
        for (int s = tid; s < 1024; s += 512) {                                   \
            int k = s >> 4, n4 = s & 15;                                          \
            cpa16(W2U + (uint32_t)(k * 72 + n4 * 4) * 4,                          \
                  g_wr + W2R_OFF + k * 896 + nb + n4 * 4);                        \
        }                                                                         \
        CPA_COMMIT();                                                             \
    } } while (0)

    // G1: W1 -> Bm
    for (int s = tid; s < 1024; s += 512) {
        int k = s >> 4, n4 = s & 15;
        cpa16(BmU + (uint32_t)(k * 72 + n4 * 4) * 4, g_wr + W1R_OFF + k * 64 + n4 * 4);
    }
    CPA_COMMIT();
    // G2: W2cols(0) = wB cols 256.. -> W2t
    for (int s = tid; s < 1024; s += 512) {
        int k = s >> 4, n4 = s & 15;
        cpa16(W2U + (uint32_t)(k * 72 + n4 * 4) * 4, g_wr + W2R_OFF + k * 896 + 256 + n4 * 4);
    }
    CPA_COMMIT();
    if (tid < 256) {
        int ge = e0 + (tid >> 2);
        ysm[tid] = (ge < E) ? eattr[(size_t)ge * 4 + (tid & 3)] : 0.f;
    }
    for (int qd = tid; qd < 1024; qd += 512) {
        int mt = qd >> 8, kg = (qd >> 5) & 7, ln = qd & 31;
        int ea = e0 + mt * 16 + (ln >> 2), ka = kg * 8 + (ln & 3);
        int eb = ea + 8;
        float v00 = (ea < E) ? es[(size_t)ea * 64 + ka] : 0.f;
        float v01 = (ea < E) ? es[(size_t)ea * 64 + ka + 4] : 0.f;
        float v10 = (eb < E) ? es[(size_t)eb * 64 + ka] : 0.f;
        float v11 = (eb < E) ? es[(size_t)eb * 64 + ka + 4] : 0.f;
        Ah4[qd] = make_float4(tf32r(v00), tf32r(v01), tf32r(v10), tf32r(v11));
    }
    CPA_WAIT1();
    __syncthreads();

    H_STAGE(sm, Ah4, Bm, redS, redQ)

    float accR[2][2][4];
    float accM[3][2][2][4];
#pragma unroll
    for (int mt = 0; mt < 2; mt++)
#pragma unroll
        for (int nt = 0; nt < 2; nt++)
#pragma unroll
            for (int f = 0; f < 4; f++) {
                accR[mt][nt][f] = 0.f;
#pragma unroll
                for (int m = 0; m < 3; m++) accM[m][mt][nt][f] = 0.f;
            }

    for (int q = 0; q < Q; q++) {
        CPA_WAIT1();
        __syncthreads();
        {
            int base = (q < 4) ? 256 + q * 64 : (q < 6 ? 512 + (q - 4) * 64
                                                       : 768 + (q - 6) * 64);
            W_STAGE(Ah4, W2t, wsm, base)
        }
        // build A planes
        if (q < 4) {
            for (int qd = tid; qd < 1024; qd += 512) {
                int mt = qd >> 8, kg = (qd >> 5) & 7, ln = qd & 31;
                int ea = mt * 16 + (ln >> 2), ka = kg * 8 + (ln & 3);
                float v[4];
#pragma unroll
                for (int t = 0; t < 4; t++) {
                    int e = ea + (t >> 1) * 8, kk = ka + (t & 1) * 4;
                    int ge = e0 + e;
                    v[t] = (ge < E)
                         ? node[(size_t)ge * 640 + q * 64 + kk] * wsm[e * 68 + kk]
                         : 0.f;
                }
                A04[qd] = make_float4(tf32r(v[0]), tf32r(v[1]), tf32r(v[2]), tf32r(v[3]));
            }
        } else {
            for (int qd = tid; qd < 1024; qd += 512) {
                int mt = qd >> 8, kg = (qd >> 5) & 7, ln = qd & 31;
                int ea = mt * 16 + (ln >> 2), ka = kg * 8 + (ln & 3);
                float a0[4], a1[4], a2[4];
#pragma unroll
                for (int t = 0; t < 4; t++) {
                    int e = ea + (t >> 1) * 8, kk = ka + (t & 1) * 4;
                    int ge = e0 + e;
                    a0[t] = a1[t] = a2[t] = 0.f;
                    if (ge < E) {
                        if (q < 6) {
                            int j = (q - 4) * 64 + kk;
                            const float* xp = node + (size_t)ge * 640 + 256 + 3 * j;
                            float f = ysm[e * 4] * wsm[e * 68 + kk];
                            a0[t] = xp[0] * f; a1[t] = xp[1] * f; a2[t] = xp[2] * f;
                        } else {
                            int j = (q - 6) * 64 + kk;
                            const float* xp = node + (size_t)ge * 640 + 256 + 3 * j;
                            float x0v = xp[0], x1v = xp[1], x2v = xp[2];
                            float z0 = ysm[e * 4 + 1], z1 = ysm[e * 4 + 2], z2 = ysm[e * 4 + 3];
                            float f = S2 * wsm[e * 68 + kk];
                            a0[t] = (x1v * z2 - x2v * z1) * f;
                            a1[t] = (x2v * z0 - x0v * z2) * f;
                            a2[t] = (x0v * z1 - x1v * z0) * f;
                        }
                    }
                }
                A04[qd] = make_float4(tf32r(a0[0]), tf32r(a0[1]), tf32r(a0[2]), tf32r(a0[3]));
                A14[qd] = make_float4(tf32r(a1[0]), tf32r(a1[1]), tf32r(a1[2]), tf32r(a1[3]));
                A24[qd] = make_float4(tf32r(a2[0]), tf32r(a2[1]), tf32r(a2[2]), tf32r(a2[3]));
            }
        }
        if (q + 1 < Q) CPA_WAIT1(); else CPA_WAIT0();
        __syncthreads();
        if (q < 4) {
#pragma unroll
            for (int ks = 0; ks < 8; ks++) {
                uint32_t a0[4], a1[4];
                ldApk(a0, A04, wm * 2, ks, lane);
                ldApk(a1, A04, wm * 2 + 1, ks, lane);
#pragma unroll
                for (int nt = 0; nt < 2; nt++) {
                    uint32_t b[2];
                    ldBk(b, Bm, 136, n0 + nt * 8, ks * 8, qr, qc);
                    mma8(accR[0][nt], a0, b);
                    mma8(accR[1][nt], a1, b);
                }
            }
        } else {
#pragma unroll
            for (int ks = 0; ks < 8; ks++) {
                uint32_t b[2][2];
#pragma unroll
                for (int nt = 0; nt < 2; nt++) ldBk(b[nt], Bm, 136, n0 + nt * 8, ks * 8, qr, qc);
                const float4* Ap[3] = {A04, A14, A24};
#pragma unroll
                for (int m = 0; m < 3; m++) {
                    uint32_t a0[4], a1[4];
                    ldApk(a0, Ap[m], wm * 2, ks, lane);
                    ldApk(a1, Ap[m], wm * 2 + 1, ks, lane);
#pragma unroll
                    for (int nt = 0; nt < 2; nt++) {
                        mma8(accM[m][0][nt], a0, b[nt]);
                        mma8(accM[m][1][nt], a1, b[nt]);
                    }
                }
            }
        }
        __syncthreads();
        if (q + 1 < Q) COMMIT_BMAIN(q + 1);
    }

    // epilogue: fold R plane, sumsq, norm, write
#pragma unroll
    for (int mt = 0; mt < 2; mt++)
#pragma unroll
        for (int h = 0; h < 2; h++) {
            int e = wm * 32 + mt * 16 + qr + h * 8;
            float z0 = ysm[e * 4 + 1], z1 = ysm[e * 4 + 2], z2 = ysm[e * 4 + 3];
            float s = 0.f;
#pragma unroll
            for (int nt = 0; nt < 2; nt++)
#pragma unroll
                for (int c = 0; c < 2; c++) {
                    float R = accR[mt][nt][h * 2 + c];
                    float v0 = z0 * R + accM[0][mt][nt][h * 2 + c];
                    float v1 = z1 * R + accM[1][mt][nt][h * 2 + c];
                    float v2 = z2 * R + accM[2][mt][nt][h * 2 + c];
                    accM[0][mt][nt][h * 2 + c] = v0;
                    accM[1][mt][nt][h * 2 + c] = v1;
                    accM[2][mt][nt][h * 2 + c] = v2;
                    s += v0 * v0 + v1 * v1 + v2 * v2;
                }
            s = quad_sum(s);
            if (qc == 0) redQ[e * 8 + wn] = s;
        }
    __syncthreads();
    float cg[4];
#pragma unroll
    for (int nt = 0; nt < 2; nt++)
#pragma unroll
        for (int c = 0; c < 2; c++) cg[nt * 2 + c] = gv[n0 + nt * 8 + qc * 2 + c];
#pragma unroll
    for (int mt = 0; mt < 2; mt++)
#pragma unroll
        for (int h = 0; h < 2; h++) {
            int e = wm * 32 + mt * 16 + qr + h * 8, ge = e0 + e;
            float qt = 0.f;
#pragma unroll
            for (int w8 = 0; w8 < 8; w8++) qt += redQ[e * 8 + w8];
            float rstd = rsqrtf(qt * (1.f / 384.f) + EPS);
            if (ge < E) {
                float* ob = out + (size_t)ge * 640 + 256;
#pragma unroll
                for (int nt = 0; nt < 2; nt++)
#pragma unroll
                    for (int c = 0; c < 2; c++) {
                        int col = n0 + nt * 8 + qc * 2 + c;
                        float g = cg[nt * 2 + c] * rstd;
                        ob[3 * col + 0] = accM[0][mt][nt][h * 2 + c] * g;
                        ob[3 * col + 1] = accM[1][mt][nt][h * 2 + c] * g;
                        ob[3 * col + 2] = accM[2][mt][nt][h * 2 + c] * g;
                    }
            }
        }
#undef COMMIT_BMAIN
#undef COMMIT_W2_NEXT
}

// ---------------------------------------------------------------------------
extern "C" void kernel_launch(void* const* d_in, const int* in_sizes, int n_in,
                              void* d_out, int out_size)
{
    const float* node  = (const float*)d_in[0];   // (E, 640)
    const float* eattr = (const float*)d_in[1];   // (E, 4)
    const float* escal = (const float*)d_in[2];   // (E, 64)
    const float* rW1   = (const float*)d_in[3];   // (64, 64)
    const float* rb1   = (const float*)d_in[4];   // (64,)
    const float* rlg   = (const float*)d_in[5];   // (64,)
    const float* rlb   = (const float*)d_in[6];   // (64,)
    const float* rW2   = (const float*)d_in[7];   // (64, 896)
    const float* roff  = (const float*)d_in[8];   // (896,)
    const float* Ws    = (const float*)d_in[9];   // (384, 256)
    const float* bs    = (const float*)d_in[10];  // (256,)
    const float* Wv    = (const float*)d_in[11];  // (512, 128)
    const float* gs    = (const float*)d_in[12];  // (256,)
    const float* gb    = (const float*)d_in[13];  // (256,)
    const float* gv    = (const float*)d_in[14];  // (128,)
    float* out = (float*)d_out;

    const int E = in_sizes[1] / 4;
    const int nb64 = (E + 63) / 64;

    cudaFuncSetAttribute(f2_s, cudaFuncAttributeMaxDynamicSharedMemorySize, F2_SMEM);
    cudaFuncSetAttribute(f3_v, cudaFuncAttributeMaxDynamicSharedMemorySize, F3_SMEM);

    k0_round<<<880, 256>>>(rW1, rW2, Ws, Wv);
    f2_s<<<nb64, 512, F2_SMEM>>>(node, eattr, escal, rb1, rlg, rlb, roff,
                                 bs, gs, gb, out, E);
    f3_v<<<nb64, 512, F3_SMEM>>>(node, eattr, escal, rb1, rlg, rlb, roff,
                                 gv, out, E);
}